// round 2
// baseline (speedup 1.0000x reference)
#include <cuda_runtime.h>

// ---------- scratch (__device__ globals; no allocation allowed) ----------
__device__ float g_part[128];
__device__ float g_mvec[64];                 // mean * colsum(wqk)
__device__ float g_QT[4 * 64 * 4096];        // [w][d][n]  d-major normalized Q
__device__ float g_V [4 * 4096 * 64];        // [w][n][c]
__device__ float g_attn[1048576];            // [w][n][c] == raw reshape to (64,128,128)
__device__ float g_t [1048576];              // x + attn branch
__device__ float g_z1[1048576];
__device__ float g_z2[1048576];
__device__ float g_w1T[64 * 9 * 64];         // [ci][tap][co]
__device__ float g_w2T[64 * 9 * 64];
__device__ float g_w3T[64 * 64];             // [ci][co]
__device__ float g_wlT[65 * 64];             // [ci][co]

// ---------- weight transposes ----------
__global__ void prep_w(const float* __restrict__ w1, const float* __restrict__ w2,
                       const float* __restrict__ w3, const float* __restrict__ wl) {
    int i = blockIdx.x * 256 + threadIdx.x;   // 144 blocks -> [0,36864)
    {
        int co = i / 576, r = i - co * 576;   // r = ci*9+tap
        g_w1T[r * 64 + co] = w1[i];
        g_w2T[r * 64 + co] = w2[i];
    }
    if (i < 4096) { int co = i >> 6, ci = i & 63; g_w3T[ci * 64 + co] = w3[i]; }
    if (i < 4160) { int co = i / 65, ci = i - co * 65; g_wlT[ci * 64 + co] = wl[i]; }
}

// ---------- global mean of x (2-stage, deterministic) ----------
__global__ void mean1(const float* __restrict__ x) {
    __shared__ float red[256];
    int t = threadIdx.x;
    int base = blockIdx.x * 8192;
    float s = 0.f;
#pragma unroll
    for (int k = 0; k < 32; k++) s += x[base + k * 256 + t];
    red[t] = s; __syncthreads();
    for (int o = 128; o; o >>= 1) { if (t < o) red[t] += red[t + o]; __syncthreads(); }
    if (t == 0) g_part[blockIdx.x] = red[0];
}

__global__ void mean2(const float* __restrict__ wqk) {
    __shared__ float red[128];
    __shared__ float m_sh;
    int t = threadIdx.x;
    red[t] = g_part[t]; __syncthreads();
    for (int o = 64; o; o >>= 1) { if (t < o) red[t] += red[t + o]; __syncthreads(); }
    if (t == 0) m_sh = red[0] * (1.0f / 1048576.0f);
    __syncthreads();
    if (t < 64) {
        float cs = 0.f;
        for (int c = 0; c < 64; c++) cs += wqk[c * 64 + t];
        g_mvec[t] = m_sh * cs;
    }
}

// ---------- build normalized Q (d-major) and V per window ----------
__global__ void qv_build(const float* __restrict__ x, const float* __restrict__ wqk) {
    __shared__ float wqk_s[4096];
    __shared__ float xs[32 * 65];
    __shared__ float qs[32 * 65];
    __shared__ float red[8];
    int b = blockIdx.x;                 // 512 blocks
    int w = b >> 7, rb = b & 127;
    int hs = rb >> 1, wsb = (rb & 1) * 32;
    int dh = w >> 1, dw = w & 1;
    int t = threadIdx.x;
    for (int i = t; i < 4096; i += 256) wqk_s[i] = wqk[i];
    int h = 2 * hs + dh;
    for (int i = t; i < 2048; i += 256) {
        int c = i >> 5, j = i & 31;
        int wp = 2 * (wsb + j) + dw;
        xs[j * 65 + c] = x[c * 16384 + h * 128 + wp];
    }
    __syncthreads();
    int nbase = hs * 64 + wsb;
    for (int i = t; i < 2048; i += 256) {           // V = raw x, window layout
        int c = i & 63, j = i >> 6;
        g_V[(w * 4096 + nbase + j) * 64 + c] = xs[j * 65 + c];
    }
    int e = t & 63, jg = t >> 6;
    float mv = g_mvec[e];
    int lane = t & 31, warp = t >> 5;
    for (int jj = jg; jj < 32; jj += 4) {
        float u = 0.f;
#pragma unroll 8
        for (int c = 0; c < 64; c++) u = fmaf(xs[jj * 65 + c], wqk_s[c * 64 + e], u);
        u -= mv;
        float ss = u * u;
#pragma unroll
        for (int o = 16; o; o >>= 1) ss += __shfl_xor_sync(0xFFFFFFFFu, ss, o);
        if (lane == 0) red[warp] = ss;
        __syncthreads();
        float n2 = red[2 * jg] + red[2 * jg + 1];
        qs[jj * 65 + e] = u * rsqrtf(n2 + 1e-24f);
        __syncthreads();
    }
    for (int i = t; i < 2048; i += 256) {           // QT[w][e][n]
        int j = i & 31, ee = i >> 5;
        g_QT[(w * 64 + ee) * 4096 + nbase + j] = qs[j * 65 + ee];
    }
}

// exp((dot+1)/8) via degree-4 Taylor; s in [0,0.25]
__device__ __forceinline__ float exp_attn(float dot) {
    float s = fmaf(dot, 0.125f, 0.125f);
    float e = fmaf(s, 0.041666668f, 0.16666667f);
    e = fmaf(s, e, 0.5f);
    e = fmaf(s, e, 1.0f);
    e = fmaf(s, e, 1.0f);
    return e;
}

// ---------- attention: 64q tile x 64k chunks, no-max softmax ----------
__global__ void __launch_bounds__(256, 2) attn_kernel() {
    __shared__ float sm[12288];                 // exactly 48KB
    float* QsT = sm;                            // [64 d][64 q]
    float* KPs = sm + 4096;                     // K tile [d][k], reused as P [k][q]
    float* Vs  = sm + 8192;                     // [64 k][64 c]
    float* rs  = sm;                            // aliases QsT after mainloop
    const float4* QsT4 = (const float4*)QsT;
    const float4* KPs4 = (const float4*)KPs;
    const float4* Vs4  = (const float4*)Vs;
    float4* Ps4 = (float4*)KPs;

    int w = blockIdx.y;
    int qb = blockIdx.x * 64;
    int t = threadIdx.x;
    int j = t & 63, dq = t >> 6;
    int tq = t & 15, tk = t >> 4;
    int qrow = t & 63, seg = t >> 6;

#pragma unroll
    for (int pass = 0; pass < 16; pass++) {
        int d = pass * 4 + dq;
        QsT[d * 64 + j] = g_QT[(w * 64 + d) * 4096 + qb + j];
    }

    float o[4][4];
#pragma unroll
    for (int i = 0; i < 4; i++)
#pragma unroll
        for (int c = 0; c < 4; c++) o[i][c] = 0.f;
    float rsum = 0.f;

    for (int kb = 0; kb < 4096; kb += 64) {
        __syncthreads();
#pragma unroll
        for (int pass = 0; pass < 16; pass++) {
            int d = pass * 4 + dq;
            KPs[d * 64 + j] = g_QT[(w * 64 + d) * 4096 + kb + j];
        }
#pragma unroll
        for (int pass = 0; pass < 16; pass++) {
            int k = pass * 4 + dq;
            Vs[k * 64 + j] = g_V[(w * 4096 + kb + k) * 64 + j];
        }
        __syncthreads();

        float s00=0,s01=0,s02=0,s03=0, s10=0,s11=0,s12=0,s13=0;
        float s20=0,s21=0,s22=0,s23=0, s30=0,s31=0,s32=0,s33=0;
#pragma unroll 16
        for (int d = 0; d < 64; d++) {
            float4 q = QsT4[d * 16 + tq];
            float4 k = KPs4[d * 16 + tk];
            s00 = fmaf(q.x, k.x, s00); s01 = fmaf(q.x, k.y, s01); s02 = fmaf(q.x, k.z, s02); s03 = fmaf(q.x, k.w, s03);
            s10 = fmaf(q.y, k.x, s10); s11 = fmaf(q.y, k.y, s11); s12 = fmaf(q.y, k.z, s12); s13 = fmaf(q.y, k.w, s13);
            s20 = fmaf(q.z, k.x, s20); s21 = fmaf(q.z, k.y, s21); s22 = fmaf(q.z, k.z, s22); s23 = fmaf(q.z, k.w, s23);
            s30 = fmaf(q.w, k.x, s30); s31 = fmaf(q.w, k.y, s31); s32 = fmaf(q.w, k.z, s32); s33 = fmaf(q.w, k.w, s33);
        }
        __syncthreads();   // all K reads complete before P overwrites the buffer
        Ps4[(4 * tk + 0) * 16 + tq] = make_float4(exp_attn(s00), exp_attn(s10), exp_attn(s20), exp_attn(s30));
        Ps4[(4 * tk + 1) * 16 + tq] = make_float4(exp_attn(s01), exp_attn(s11), exp_attn(s21), exp_attn(s31));
        Ps4[(4 * tk + 2) * 16 + tq] = make_float4(exp_attn(s02), exp_attn(s12), exp_attn(s22), exp_attn(s32));
        Ps4[(4 * tk + 3) * 16 + tq] = make_float4(exp_attn(s03), exp_attn(s13), exp_attn(s23), exp_attn(s33));
        __syncthreads();

        float rp = 0.f;                      // rowsum partial, fixed ownership
#pragma unroll
        for (int kk = 0; kk < 16; kk++) rp += KPs[(seg * 16 + kk) * 64 + qrow];
        rsum += rp;

#pragma unroll 16
        for (int k = 0; k < 64; k++) {       // O += P^T @ V
            float4 p = KPs4[k * 16 + tq];
            float4 v = Vs4[k * 16 + tk];
            o[0][0] = fmaf(p.x, v.x, o[0][0]); o[0][1] = fmaf(p.x, v.y, o[0][1]); o[0][2] = fmaf(p.x, v.z, o[0][2]); o[0][3] = fmaf(p.x, v.w, o[0][3]);
            o[1][0] = fmaf(p.y, v.x, o[1][0]); o[1][1] = fmaf(p.y, v.y, o[1][1]); o[1][2] = fmaf(p.y, v.z, o[1][2]); o[1][3] = fmaf(p.y, v.w, o[1][3]);
            o[2][0] = fmaf(p.z, v.x, o[2][0]); o[2][1] = fmaf(p.z, v.y, o[2][1]); o[2][2] = fmaf(p.z, v.z, o[2][2]); o[2][3] = fmaf(p.z, v.w, o[2][3]);
            o[3][0] = fmaf(p.w, v.x, o[3][0]); o[3][1] = fmaf(p.w, v.y, o[3][1]); o[3][2] = fmaf(p.w, v.z, o[3][2]); o[3][3] = fmaf(p.w, v.w, o[3][3]);
        }
    }
    __syncthreads();
    rs[seg * 64 + qrow] = rsum;
    __syncthreads();
#pragma unroll
    for (int i = 0; i < 4; i++) {
        int q = 4 * tq + i;
        float inv = 1.0f / (rs[q] + rs[64 + q] + rs[128 + q] + rs[192 + q]);
        ((float4*)g_attn)[w * 65536 + (qb + q) * 16 + tk] =
            make_float4(o[i][0] * inv, o[i][1] * inv, o[i][2] * inv, o[i][3] * inv);
    }
}

// ---------- fused 1x1 conv (attn 64ch + unet 1ch) + bias + residual -> g_t ----------
__global__ void convl_fused(const float* __restrict__ unet, const float* __restrict__ x,
                            const float* __restrict__ bias) {
    __shared__ float w_s[4160];
    int t = threadIdx.x;
    for (int i = t; i < 4160; i += 256) w_s[i] = g_wlT[i];
    __syncthreads();
    int p = blockIdx.x * 128 + (t & 127);
    int cog = t >> 7;
    float acc[32];
#pragma unroll
    for (int i = 0; i < 32; i++) acc[i] = 0.f;
    for (int ci = 0; ci < 65; ci++) {
        float v = (ci < 64) ? g_attn[ci * 16384 + p] : unet[p];
        const float4* wr = (const float4*)(w_s + ci * 64 + cog * 32);
#pragma unroll
        for (int k = 0; k < 8; k++) {
            float4 wv = wr[k];
            acc[4 * k + 0] = fmaf(wv.x, v, acc[4 * k + 0]);
            acc[4 * k + 1] = fmaf(wv.y, v, acc[4 * k + 1]);
            acc[4 * k + 2] = fmaf(wv.z, v, acc[4 * k + 2]);
            acc[4 * k + 3] = fmaf(wv.w, v, acc[4 * k + 3]);
        }
    }
#pragma unroll
    for (int i = 0; i < 32; i++) {
        int co = cog * 32 + i;
        g_t[co * 16384 + p] = x[co * 16384 + p] + acc[i] + bias[co];
    }
}

// ---------- tiled 3x3 conv (dilation D) + relu ----------
template <int D>
__global__ void conv3x3(const float* __restrict__ in, const float* __restrict__ wT,
                        const float* __restrict__ bias, float* __restrict__ out) {
    constexpr int IH = 8 + 2 * D, IW = 16 + 2 * D;
    __shared__ float in_s[8 * IH * IW];
    __shared__ float w_s[8 * 9 * 64];
    int t = threadIdx.x;
    int p = t & 127, cog = t >> 7;
    int r = p >> 4, c = p & 15;
    int r0 = blockIdx.y * 8, c0 = blockIdx.x * 16;
    float acc[32];
#pragma unroll
    for (int i = 0; i < 32; i++) acc[i] = bias[cog * 32 + i];
    for (int cib = 0; cib < 64; cib += 8) {
        __syncthreads();
        for (int idx = t; idx < 8 * IH * IW; idx += 256) {
            int ci = idx / (IH * IW), rem = idx - ci * (IH * IW);
            int rr = rem / IW, cc = rem - rr * IW;
            int gr = r0 - D + rr, gc = c0 - D + cc;
            float v = 0.f;
            if (gr >= 0 && gr < 128 && gc >= 0 && gc < 128)
                v = in[(cib + ci) * 16384 + gr * 128 + gc];
            in_s[idx] = v;
        }
        for (int idx = t; idx < 8 * 576; idx += 256) w_s[idx] = wT[cib * 576 + idx];
        __syncthreads();
#pragma unroll
        for (int ci = 0; ci < 8; ci++) {
#pragma unroll
            for (int kh = 0; kh < 3; kh++) {
#pragma unroll
                for (int kw = 0; kw < 3; kw++) {
                    float v = in_s[ci * IH * IW + (r + kh * D) * IW + (c + kw * D)];
                    const float4* wr = (const float4*)(w_s + (ci * 9 + kh * 3 + kw) * 64 + cog * 32);
#pragma unroll
                    for (int q = 0; q < 8; q++) {
                        float4 wv = wr[q];
                        acc[4 * q + 0] = fmaf(v, wv.x, acc[4 * q + 0]);
                        acc[4 * q + 1] = fmaf(v, wv.y, acc[4 * q + 1]);
                        acc[4 * q + 2] = fmaf(v, wv.z, acc[4 * q + 2]);
                        acc[4 * q + 3] = fmaf(v, wv.w, acc[4 * q + 3]);
                    }
                }
            }
        }
    }
    int gp = (r0 + r) * 128 + c0 + c;
#pragma unroll
    for (int i = 0; i < 32; i++)
        out[(cog * 32 + i) * 16384 + gp] = fmaxf(acc[i], 0.f);
}

// ---------- final 1x1 conv + bias + residual -> d_out ----------
__global__ void conv1x1_final(const float* __restrict__ x, const float* __restrict__ bias,
                              float* __restrict__ out) {
    __shared__ float w_s[4096];
    int t = threadIdx.x;
    for (int i = t; i < 4096; i += 256) w_s[i] = g_w3T[i];
    __syncthreads();
    int p = blockIdx.x * 128 + (t & 127);
    int cog = t >> 7;
    float acc[32];
#pragma unroll
    for (int i = 0; i < 32; i++) acc[i] = 0.f;
    for (int ci = 0; ci < 64; ci++) {
        float v = g_z2[ci * 16384 + p];
        const float4* wr = (const float4*)(w_s + ci * 64 + cog * 32);
#pragma unroll
        for (int k = 0; k < 8; k++) {
            float4 wv = wr[k];
            acc[4 * k + 0] = fmaf(wv.x, v, acc[4 * k + 0]);
            acc[4 * k + 1] = fmaf(wv.y, v, acc[4 * k + 1]);
            acc[4 * k + 2] = fmaf(wv.z, v, acc[4 * k + 2]);
            acc[4 * k + 3] = fmaf(wv.w, v, acc[4 * k + 3]);
        }
    }
#pragma unroll
    for (int i = 0; i < 32; i++) {
        int co = cog * 32 + i;
        out[co * 16384 + p] = x[co * 16384 + p] + acc[i] + bias[co];
    }
}

extern "C" void kernel_launch(void* const* d_in, const int* in_sizes, int n_in,
                              void* d_out, int out_size) {
    const float* x     = (const float*)d_in[0];
    const float* unet  = (const float*)d_in[1];
    const float* wqk   = (const float*)d_in[2];
    const float* c1w   = (const float*)d_in[3];
    const float* c1b   = (const float*)d_in[4];
    const float* c2w   = (const float*)d_in[5];
    const float* c2b   = (const float*)d_in[6];
    const float* c3w   = (const float*)d_in[7];
    const float* c3b   = (const float*)d_in[8];
    const float* clw   = (const float*)d_in[9];
    const float* clb   = (const float*)d_in[10];
    float* out = (float*)d_out;

    prep_w<<<144, 256>>>(c1w, c2w, c3w, clw);
    mean1<<<128, 256>>>(x);
    mean2<<<1, 128>>>(wqk);
    qv_build<<<512, 256>>>(x, wqk);
    attn_kernel<<<dim3(64, 4), 256>>>();
    convl_fused<<<128, 256>>>(unet, x, clb);
    float* z1; cudaGetSymbolAddress((void**)&z1, g_z1);
    float* z2; cudaGetSymbolAddress((void**)&z2, g_z2);
    float* tt; cudaGetSymbolAddress((void**)&tt, g_t);
    float* w1T; cudaGetSymbolAddress((void**)&w1T, g_w1T);
    float* w2T; cudaGetSymbolAddress((void**)&w2T, g_w2T);
    conv3x3<1><<<dim3(8, 16), 256>>>(tt, w1T, c1b, z1);
    conv3x3<2><<<dim3(8, 16), 256>>>(z1, w2T, c2b, z2);
    conv1x1_final<<<128, 256>>>(x, c3b, out);
}

// round 3
// speedup vs baseline: 2.3340x; 2.3340x over previous
#include <cuda_runtime.h>
#include <cuda_bf16.h>

// ---------- scratch ----------
__device__ float g_part[128];
__device__ float g_mvec[64];                               // mean * colsum(wqk)
__device__ __align__(16) __nv_bfloat16 g_Qb[4 * 4096 * 64]; // [w][n][d] normalized Q (=K)
__device__ __align__(16) __nv_bfloat16 g_Vb[4 * 4096 * 64]; // [w][n][c]
__device__ float g_attn[1048576];                           // [w][n][c] == raw reshape (64,128,128)
__device__ float g_t [1048576];
__device__ float g_z1[1048576];
__device__ float g_z2[1048576];
__device__ float g_w1T[64 * 9 * 64];
__device__ float g_w2T[64 * 9 * 64];
__device__ float g_w3T[64 * 64];
__device__ float g_wlT[65 * 64];

// ---------- weight transposes ----------
__global__ void prep_w(const float* __restrict__ w1, const float* __restrict__ w2,
                       const float* __restrict__ w3, const float* __restrict__ wl) {
    int i = blockIdx.x * 256 + threadIdx.x;
    {
        int co = i / 576, r = i - co * 576;
        g_w1T[r * 64 + co] = w1[i];
        g_w2T[r * 64 + co] = w2[i];
    }
    if (i < 4096) { int co = i >> 6, ci = i & 63; g_w3T[ci * 64 + co] = w3[i]; }
    if (i < 4160) { int co = i / 65, ci = i - co * 65; g_wlT[ci * 64 + co] = wl[i]; }
}

// ---------- global mean ----------
__global__ void mean1(const float* __restrict__ x) {
    __shared__ float red[256];
    int t = threadIdx.x;
    int base = blockIdx.x * 8192;
    float s = 0.f;
#pragma unroll
    for (int k = 0; k < 32; k++) s += x[base + k * 256 + t];
    red[t] = s; __syncthreads();
    for (int o = 128; o; o >>= 1) { if (t < o) red[t] += red[t + o]; __syncthreads(); }
    if (t == 0) g_part[blockIdx.x] = red[0];
}

__global__ void mean2(const float* __restrict__ wqk) {
    __shared__ float red[128];
    __shared__ float m_sh;
    int t = threadIdx.x;
    red[t] = g_part[t]; __syncthreads();
    for (int o = 64; o; o >>= 1) { if (t < o) red[t] += red[t + o]; __syncthreads(); }
    if (t == 0) m_sh = red[0] * (1.0f / 1048576.0f);
    __syncthreads();
    if (t < 64) {
        float cs = 0.f;
        for (int c = 0; c < 64; c++) cs += wqk[c * 64 + t];
        g_mvec[t] = m_sh * cs;
    }
}

// ---------- build normalized Q (bf16, n-major) and V (bf16) ----------
__global__ void qv_build(const float* __restrict__ x, const float* __restrict__ wqk) {
    __shared__ float wqk_s[4096];
    __shared__ float xs[32 * 65];
    __shared__ float qs[32 * 65];
    __shared__ float red[8];
    int b = blockIdx.x;                 // 512 blocks
    int w = b >> 7, rb = b & 127;
    int hs = rb >> 1, wsb = (rb & 1) * 32;
    int dh = w >> 1, dw = w & 1;
    int t = threadIdx.x;
    for (int i = t; i < 4096; i += 256) wqk_s[i] = wqk[i];
    int h = 2 * hs + dh;
    for (int i = t; i < 2048; i += 256) {
        int c = i >> 5, j = i & 31;
        int wp = 2 * (wsb + j) + dw;
        xs[j * 65 + c] = x[c * 16384 + h * 128 + wp];
    }
    __syncthreads();
    int nbase = hs * 64 + wsb;
    for (int i = t; i < 2048; i += 256) {           // V bf16, window layout
        int c = i & 63, j = i >> 6;
        g_Vb[(w * 4096 + nbase + j) * 64 + c] = __float2bfloat16(xs[j * 65 + c]);
    }
    int e = t & 63, jg = t >> 6;
    float mv = g_mvec[e];
    int lane = t & 31, warp = t >> 5;
    for (int jj = jg; jj < 32; jj += 4) {
        float u = 0.f;
#pragma unroll 8
        for (int c = 0; c < 64; c++) u = fmaf(xs[jj * 65 + c], wqk_s[c * 64 + e], u);
        u -= mv;
        float ss = u * u;
#pragma unroll
        for (int o = 16; o; o >>= 1) ss += __shfl_xor_sync(0xFFFFFFFFu, ss, o);
        if (lane == 0) red[warp] = ss;
        __syncthreads();
        float n2 = red[2 * jg] + red[2 * jg + 1];
        qs[jj * 65 + e] = u * rsqrtf(n2 + 1e-24f);
        __syncthreads();
    }
    for (int i = t; i < 2048; i += 256) {
        int c = i & 63, j = i >> 6;
        g_Qb[(w * 4096 + nbase + j) * 64 + c] = __float2bfloat16(qs[j * 65 + c]);
    }
}

// exp((dot+1)/8), degree-4 Taylor, s in [0,0.25]
__device__ __forceinline__ float exp_attn(float dot) {
    float s = fmaf(dot, 0.125f, 0.125f);
    float e = fmaf(s, 0.041666668f, 0.16666667f);
    e = fmaf(s, e, 0.5f);
    e = fmaf(s, e, 1.0f);
    e = fmaf(s, e, 1.0f);
    return e;
}

// ---------- mma helpers ----------
__device__ __forceinline__ void ldsm4(unsigned addr, unsigned& r0, unsigned& r1,
                                      unsigned& r2, unsigned& r3) {
    asm volatile("ldmatrix.sync.aligned.m8n8.x4.shared.b16 {%0,%1,%2,%3}, [%4];"
                 : "=r"(r0), "=r"(r1), "=r"(r2), "=r"(r3) : "r"(addr));
}
__device__ __forceinline__ void ldsm4t(unsigned addr, unsigned& r0, unsigned& r1,
                                       unsigned& r2, unsigned& r3) {
    asm volatile("ldmatrix.sync.aligned.m8n8.x4.trans.shared.b16 {%0,%1,%2,%3}, [%4];"
                 : "=r"(r0), "=r"(r1), "=r"(r2), "=r"(r3) : "r"(addr));
}
__device__ __forceinline__ void mma16816(float* c, const unsigned* a, unsigned b0, unsigned b1) {
    asm volatile("mma.sync.aligned.m16n8k16.row.col.f32.bf16.bf16.f32 "
                 "{%0,%1,%2,%3},{%4,%5,%6,%7},{%8,%9},{%0,%1,%2,%3};"
                 : "+f"(c[0]), "+f"(c[1]), "+f"(c[2]), "+f"(c[3])
                 : "r"(a[0]), "r"(a[1]), "r"(a[2]), "r"(a[3]), "r"(b0), "r"(b1));
}
__device__ __forceinline__ unsigned packbf(float lo, float hi) {
    __nv_bfloat162 h = __floats2bfloat162_rn(lo, hi);   // .x = lo half
    return *(unsigned*)&h;
}

// ---------- attention: bf16 HMMA, 128q CTA, 128k chunks ----------
#define PITCHB 144   // bytes per smem row (72 bf16)
__global__ void __launch_bounds__(256, 1) attn_mma() {
    __shared__ __nv_bfloat16 Ks[128 * 72];
    __shared__ __nv_bfloat16 Vs[128 * 72];
    int w = blockIdx.y;
    int qb = blockIdx.x * 128;
    int t = threadIdx.x, warp = t >> 5, lane = t & 31;
    int g = lane >> 2, tig = lane & 3;
    const __nv_bfloat16* Qg = g_Qb + (size_t)w * 4096 * 64;
    const __nv_bfloat16* Vg = g_Vb + (size_t)w * 4096 * 64;

    // Q A-fragments, loaded once (rows q0+g, q0+g+8)
    int q0 = qb + warp * 16;
    unsigned qa[4][4];
#pragma unroll
    for (int s = 0; s < 4; s++) {
        const __nv_bfloat16* bp = Qg + (q0 + g) * 64 + s * 16 + 2 * tig;
        qa[s][0] = *(const unsigned*)(bp);
        qa[s][1] = *(const unsigned*)(bp + 8 * 64);
        qa[s][2] = *(const unsigned*)(bp + 8);
        qa[s][3] = *(const unsigned*)(bp + 8 * 64 + 8);
    }

    float o[8][4];
#pragma unroll
    for (int i = 0; i < 8; i++)
#pragma unroll
        for (int jx = 0; jx < 4; jx++) o[i][jx] = 0.f;
    float rs0 = 0.f, rs1 = 0.f;

    unsigned ksU = (unsigned)__cvta_generic_to_shared(Ks);
    unsigned vsU = (unsigned)__cvta_generic_to_shared(Vs);
    int mi = lane >> 3, li = lane & 7;
    unsigned kOff = ((mi >> 1) * 8 + li) * PITCHB + (mi & 1) * 16;  // QK^T (non-trans)
    unsigned vOff = ((mi & 1) * 8 + li) * PITCHB + (mi >> 1) * 16;  // PV   (trans)

    for (int kb = 0; kb < 4096; kb += 128) {
        __syncthreads();
        for (int i = t; i < 1024; i += 256) {
            int r = i >> 3, cg = i & 7;
            *(uint4*)((char*)Ks + r * PITCHB + cg * 16) = *(const uint4*)(Qg + (kb + r) * 64 + cg * 8);
            *(uint4*)((char*)Vs + r * PITCHB + cg * 16) = *(const uint4*)(Vg + (kb + r) * 64 + cg * 8);
        }
        __syncthreads();

        float p[16][4];
#pragma unroll
        for (int i = 0; i < 16; i++)
#pragma unroll
            for (int jx = 0; jx < 4; jx++) p[i][jx] = 0.f;

#pragma unroll
        for (int s = 0; s < 4; s++) {
#pragma unroll
            for (int jp = 0; jp < 8; jp++) {
                unsigned r0, r1, r2, r3;
                ldsm4(ksU + jp * (16 * PITCHB) + s * 32 + kOff, r0, r1, r2, r3);
                mma16816(p[2 * jp],     qa[s], r0, r1);
                mma16816(p[2 * jp + 1], qa[s], r2, r3);
            }
        }

        // exp + rowsum + pack P into A-fragments
        unsigned ea[8][4];
#pragma unroll
        for (int u = 0; u < 8; u++) {
            float e0 = exp_attn(p[2 * u][0]),     e1 = exp_attn(p[2 * u][1]);
            float e2 = exp_attn(p[2 * u][2]),     e3 = exp_attn(p[2 * u][3]);
            float f0 = exp_attn(p[2 * u + 1][0]), f1 = exp_attn(p[2 * u + 1][1]);
            float f2 = exp_attn(p[2 * u + 1][2]), f3 = exp_attn(p[2 * u + 1][3]);
            rs0 += (e0 + e1) + (f0 + f1);
            rs1 += (e2 + e3) + (f2 + f3);
            ea[u][0] = packbf(e0, e1);
            ea[u][1] = packbf(e2, e3);
            ea[u][2] = packbf(f0, f1);
            ea[u][3] = packbf(f2, f3);
        }

        // O += P @ V
#pragma unroll
        for (int u = 0; u < 8; u++) {
#pragma unroll
            for (int cp = 0; cp < 4; cp++) {
                unsigned r0, r1, r2, r3;
                ldsm4t(vsU + u * (16 * PITCHB) + cp * 32 + vOff, r0, r1, r2, r3);
                mma16816(o[2 * cp],     ea[u], r0, r1);
                mma16816(o[2 * cp + 1], ea[u], r2, r3);
            }
        }
    }

    rs0 += __shfl_xor_sync(0xFFFFFFFFu, rs0, 1);
    rs0 += __shfl_xor_sync(0xFFFFFFFFu, rs0, 2);
    rs1 += __shfl_xor_sync(0xFFFFFFFFu, rs1, 1);
    rs1 += __shfl_xor_sync(0xFFFFFFFFu, rs1, 2);
    float i0 = 1.f / rs0, i1 = 1.f / rs1;

    float* outp = g_attn + (size_t)(w * 4096 + q0) * 64;
#pragma unroll
    for (int c = 0; c < 8; c++) {
        int col = c * 8 + 2 * tig;
        float2 v0 = make_float2(o[c][0] * i0, o[c][1] * i0);
        float2 v1 = make_float2(o[c][2] * i1, o[c][3] * i1);
        *(float2*)(outp + g * 64 + col) = v0;
        *(float2*)(outp + (g + 8) * 64 + col) = v1;
    }
}

// ---------- fused 1x1 conv (attn 64ch + unet 1ch) + bias + residual -> g_t ----------
__global__ void convl_fused(const float* __restrict__ unet, const float* __restrict__ x,
                            const float* __restrict__ bias) {
    __shared__ float w_s[4160];
    int t = threadIdx.x;
    for (int i = t; i < 4160; i += 256) w_s[i] = g_wlT[i];
    __syncthreads();
    int p = blockIdx.x * 128 + (t & 127);
    int cog = t >> 7;
    float acc[32];
#pragma unroll
    for (int i = 0; i < 32; i++) acc[i] = 0.f;
    for (int ci = 0; ci < 65; ci++) {
        float v = (ci < 64) ? g_attn[ci * 16384 + p] : unet[p];
        const float4* wr = (const float4*)(w_s + ci * 64 + cog * 32);
#pragma unroll
        for (int k = 0; k < 8; k++) {
            float4 wv = wr[k];
            acc[4 * k + 0] = fmaf(wv.x, v, acc[4 * k + 0]);
            acc[4 * k + 1] = fmaf(wv.y, v, acc[4 * k + 1]);
            acc[4 * k + 2] = fmaf(wv.z, v, acc[4 * k + 2]);
            acc[4 * k + 3] = fmaf(wv.w, v, acc[4 * k + 3]);
        }
    }
#pragma unroll
    for (int i = 0; i < 32; i++) {
        int co = cog * 32 + i;
        g_t[co * 16384 + p] = x[co * 16384 + p] + acc[i] + bias[co];
    }
}

// ---------- tiled 3x3 conv (dilation D) + relu ----------
template <int D>
__global__ void conv3x3(const float* __restrict__ in, const float* __restrict__ wT,
                        const float* __restrict__ bias, float* __restrict__ out) {
    constexpr int IH = 8 + 2 * D, IW = 16 + 2 * D;
    __shared__ float in_s[8 * IH * IW];
    __shared__ float w_s[8 * 9 * 64];
    int t = threadIdx.x;
    int p = t & 127, cog = t >> 7;
    int r = p >> 4, c = p & 15;
    int r0 = blockIdx.y * 8, c0 = blockIdx.x * 16;
    float acc[32];
#pragma unroll
    for (int i = 0; i < 32; i++) acc[i] = bias[cog * 32 + i];
    for (int cib = 0; cib < 64; cib += 8) {
        __syncthreads();
        for (int idx = t; idx < 8 * IH * IW; idx += 256) {
            int ci = idx / (IH * IW), rem = idx - ci * (IH * IW);
            int rr = rem / IW, cc = rem - rr * IW;
            int gr = r0 - D + rr, gc = c0 - D + cc;
            float v = 0.f;
            if (gr >= 0 && gr < 128 && gc >= 0 && gc < 128)
                v = in[(cib + ci) * 16384 + gr * 128 + gc];
            in_s[idx] = v;
        }
        for (int idx = t; idx < 8 * 576; idx += 256) w_s[idx] = wT[cib * 576 + idx];
        __syncthreads();
#pragma unroll
        for (int ci = 0; ci < 8; ci++) {
#pragma unroll
            for (int kh = 0; kh < 3; kh++) {
#pragma unroll
                for (int kw = 0; kw < 3; kw++) {
                    float v = in_s[ci * IH * IW + (r + kh * D) * IW + (c + kw * D)];
                    const float4* wr = (const float4*)(w_s + (ci * 9 + kh * 3 + kw) * 64 + cog * 32);
#pragma unroll
                    for (int q = 0; q < 8; q++) {
                        float4 wv = wr[q];
                        acc[4 * q + 0] = fmaf(v, wv.x, acc[4 * q + 0]);
                        acc[4 * q + 1] = fmaf(v, wv.y, acc[4 * q + 1]);
                        acc[4 * q + 2] = fmaf(v, wv.z, acc[4 * q + 2]);
                        acc[4 * q + 3] = fmaf(v, wv.w, acc[4 * q + 3]);
                    }
                }
            }
        }
    }
    int gp = (r0 + r) * 128 + c0 + c;
#pragma unroll
    for (int i = 0; i < 32; i++)
        out[(cog * 32 + i) * 16384 + gp] = fmaxf(acc[i], 0.f);
}

// ---------- final 1x1 conv + bias + residual -> d_out ----------
__global__ void conv1x1_final(const float* __restrict__ x, const float* __restrict__ bias,
                              float* __restrict__ out) {
    __shared__ float w_s[4096];
    int t = threadIdx.x;
    for (int i = t; i < 4096; i += 256) w_s[i] = g_w3T[i];
    __syncthreads();
    int p = blockIdx.x * 128 + (t & 127);
    int cog = t >> 7;
    float acc[32];
#pragma unroll
    for (int i = 0; i < 32; i++) acc[i] = 0.f;
    for (int ci = 0; ci < 64; ci++) {
        float v = g_z2[ci * 16384 + p];
        const float4* wr = (const float4*)(w_s + ci * 64 + cog * 32);
#pragma unroll
        for (int k = 0; k < 8; k++) {
            float4 wv = wr[k];
            acc[4 * k + 0] = fmaf(wv.x, v, acc[4 * k + 0]);
            acc[4 * k + 1] = fmaf(wv.y, v, acc[4 * k + 1]);
            acc[4 * k + 2] = fmaf(wv.z, v, acc[4 * k + 2]);
            acc[4 * k + 3] = fmaf(wv.w, v, acc[4 * k + 3]);
        }
    }
#pragma unroll
    for (int i = 0; i < 32; i++) {
        int co = cog * 32 + i;
        out[co * 16384 + p] = x[co * 16384 + p] + acc[i] + bias[co];
    }
}

extern "C" void kernel_launch(void* const* d_in, const int* in_sizes, int n_in,
                              void* d_out, int out_size) {
    const float* x     = (const float*)d_in[0];
    const float* unet  = (const float*)d_in[1];
    const float* wqk   = (const float*)d_in[2];
    const float* c1w   = (const float*)d_in[3];
    const float* c1b   = (const float*)d_in[4];
    const float* c2w   = (const float*)d_in[5];
    const float* c2b   = (const float*)d_in[6];
    const float* c3w   = (const float*)d_in[7];
    const float* c3b   = (const float*)d_in[8];
    const float* clw   = (const float*)d_in[9];
    const float* clb   = (const float*)d_in[10];
    float* out = (float*)d_out;

    prep_w<<<144, 256>>>(c1w, c2w, c3w, clw);
    mean1<<<128, 256>>>(x);
    mean2<<<1, 128>>>(wqk);
    qv_build<<<512, 256>>>(x, wqk);
    attn_mma<<<dim3(32, 4), 256>>>();
    convl_fused<<<128, 256>>>(unet, x, clb);
    float* z1; cudaGetSymbolAddress((void**)&z1, g_z1);
    float* z2; cudaGetSymbolAddress((void**)&z2, g_z2);
    float* tt; cudaGetSymbolAddress((void**)&tt, g_t);
    float* w1T; cudaGetSymbolAddress((void**)&w1T, g_w1T);
    float* w2T; cudaGetSymbolAddress((void**)&w2T, g_w2T);
    conv3x3<1><<<dim3(8, 16), 256>>>(tt, w1T, c1b, z1);
    conv3x3<2><<<dim3(8, 16), 256>>>(z1, w2T, c2b, z2);
    conv1x1_final<<<128, 256>>>(x, c3b, out);
}

// round 5
// speedup vs baseline: 2.5511x; 1.0930x over previous
#include <cuda_runtime.h>
#include <cuda_bf16.h>

typedef unsigned long long u64t;

// ---------- scratch ----------
__device__ float g_part[128];
__device__ float g_mvec[64];
__device__ __align__(16) __nv_bfloat16 g_Qb[4 * 4096 * 64]; // [w][n][d] normalized Q (=K)
__device__ __align__(16) __nv_bfloat16 g_Vb[4 * 4096 * 64]; // [w][n][c]
__device__ float g_attn[1048576];                           // raw reshape (64,128,128)
__device__ float g_t [1048576];
__device__ float g_z1[1048576];
__device__ float g_z2[1048576];
__device__ float g_w1T[64 * 9 * 64];
__device__ float g_w2T[64 * 9 * 64];
__device__ float g_w3T[64 * 64];
__device__ float g_wlT[65 * 64];

// ---------- f32x2 helpers ----------
__device__ __forceinline__ u64t pk2(float a, float b) {
    u64t r; asm("mov.b64 %0,{%1,%2};" : "=l"(r) : "f"(a), "f"(b)); return r;
}
__device__ __forceinline__ void upk2(u64t v, float& a, float& b) {
    asm("mov.b64 {%0,%1},%2;" : "=f"(a), "=f"(b) : "l"(v));
}
__device__ __forceinline__ u64t fma2(u64t a, u64t b, u64t c) {
    u64t d; asm("fma.rn.f32x2 %0,%1,%2,%3;" : "=l"(d) : "l"(a), "l"(b), "l"(c)); return d;
}
__device__ __forceinline__ u64t add2(u64t a, u64t b) {
    u64t d; asm("add.rn.f32x2 %0,%1,%2;" : "=l"(d) : "l"(a), "l"(b)); return d;
}

// ---------- weight transposes ----------
__global__ void prep_w(const float* __restrict__ w1, const float* __restrict__ w2,
                       const float* __restrict__ w3, const float* __restrict__ wl) {
    int i = blockIdx.x * 256 + threadIdx.x;
    {
        int co = i / 576, r = i - co * 576;
        g_w1T[r * 64 + co] = w1[i];
        g_w2T[r * 64 + co] = w2[i];
    }
    if (i < 4096) { int co = i >> 6, ci = i & 63; g_w3T[ci * 64 + co] = w3[i]; }
    if (i < 4160) { int co = i / 65, ci = i - co * 65; g_wlT[ci * 64 + co] = wl[i]; }
}

// ---------- global mean ----------
__global__ void mean1(const float* __restrict__ x) {
    __shared__ float red[256];
    int t = threadIdx.x;
    int base = blockIdx.x * 8192;
    float s = 0.f;
#pragma unroll
    for (int k = 0; k < 32; k++) s += x[base + k * 256 + t];
    red[t] = s; __syncthreads();
    for (int o = 128; o; o >>= 1) { if (t < o) red[t] += red[t + o]; __syncthreads(); }
    if (t == 0) g_part[blockIdx.x] = red[0];
}

__global__ void mean2(const float* __restrict__ wqk) {
    __shared__ float red[128];
    __shared__ float m_sh;
    int t = threadIdx.x;
    red[t] = g_part[t]; __syncthreads();
    for (int o = 64; o; o >>= 1) { if (t < o) red[t] += red[t + o]; __syncthreads(); }
    if (t == 0) m_sh = red[0] * (1.0f / 1048576.0f);
    __syncthreads();
    if (t < 64) {
        float cs = 0.f;
        for (int c = 0; c < 64; c++) cs += wqk[c * 64 + t];
        g_mvec[t] = m_sh * cs;
    }
}

// ---------- build normalized Q (bf16) and V (bf16); warp-per-row ----------
__global__ void qv_build(const float* __restrict__ x, const float* __restrict__ wqk) {
    __shared__ float wqk_s[4096];
    __shared__ float xs[32 * 65];
    int b = blockIdx.x;                 // 512 blocks
    int w = b >> 7, rb = b & 127;
    int hs = rb >> 1, wsb = (rb & 1) * 32;
    int dh = w >> 1, dw = w & 1;
    int t = threadIdx.x;
    for (int i = t; i < 4096; i += 256) wqk_s[i] = wqk[i];
    int h = 2 * hs + dh;
    for (int i = t; i < 2048; i += 256) {
        int c = i >> 5, j = i & 31;
        int wp = 2 * (wsb + j) + dw;
        xs[j * 65 + c] = x[c * 16384 + h * 128 + wp];
    }
    __syncthreads();
    int nbase = hs * 64 + wsb;
    for (int i = t; i < 2048; i += 256) {           // V bf16
        int c = i & 63, j = i >> 6;
        g_Vb[(w * 4096 + nbase + j) * 64 + c] = __float2bfloat16(xs[j * 65 + c]);
    }
    int lane = t & 31, warp = t >> 5;
    float mv0 = g_mvec[lane], mv1 = g_mvec[lane + 32];
#pragma unroll
    for (int k = 0; k < 4; k++) {
        int jj = warp + 8 * k;
        float u0 = 0.f, u1 = 0.f;
#pragma unroll 8
        for (int c = 0; c < 64; c++) {
            float xv = xs[jj * 65 + c];
            u0 = fmaf(xv, wqk_s[c * 64 + lane], u0);
            u1 = fmaf(xv, wqk_s[c * 64 + lane + 32], u1);
        }
        u0 -= mv0; u1 -= mv1;
        float ss = u0 * u0 + u1 * u1;
#pragma unroll
        for (int o = 16; o; o >>= 1) ss += __shfl_xor_sync(0xFFFFFFFFu, ss, o);
        float rinv = rsqrtf(ss + 1e-24f);
        __nv_bfloat16* qp = g_Qb + (size_t)(w * 4096 + nbase + jj) * 64;
        qp[lane] = __float2bfloat16(u0 * rinv);
        qp[lane + 32] = __float2bfloat16(u1 * rinv);
    }
}

// ---------- mma helpers ----------
__device__ __forceinline__ void ldsm4(unsigned addr, unsigned& r0, unsigned& r1,
                                      unsigned& r2, unsigned& r3) {
    asm volatile("ldmatrix.sync.aligned.m8n8.x4.shared.b16 {%0,%1,%2,%3}, [%4];"
                 : "=r"(r0), "=r"(r1), "=r"(r2), "=r"(r3) : "r"(addr));
}
__device__ __forceinline__ void ldsm4t(unsigned addr, unsigned& r0, unsigned& r1,
                                       unsigned& r2, unsigned& r3) {
    asm volatile("ldmatrix.sync.aligned.m8n8.x4.trans.shared.b16 {%0,%1,%2,%3}, [%4];"
                 : "=r"(r0), "=r"(r1), "=r"(r2), "=r"(r3) : "r"(addr));
}
__device__ __forceinline__ void mma16816(float* c, const unsigned* a, unsigned b0, unsigned b1) {
    asm volatile("mma.sync.aligned.m16n8k16.row.col.f32.bf16.bf16.f32 "
                 "{%0,%1,%2,%3},{%4,%5,%6,%7},{%8,%9},{%0,%1,%2,%3};"
                 : "+f"(c[0]), "+f"(c[1]), "+f"(c[2]), "+f"(c[3])
                 : "r"(a[0]), "r"(a[1]), "r"(a[2]), "r"(a[3]), "r"(b0), "r"(b1));
}
__device__ __forceinline__ unsigned packbf(float lo, float hi) {
    __nv_bfloat162 h = __floats2bfloat162_rn(lo, hi);
    return *(unsigned*)&h;
}
__device__ __forceinline__ void cp16(unsigned dst, const void* src) {
    asm volatile("cp.async.cg.shared.global [%0], [%1], 16;" :: "r"(dst), "l"(src));
}

// ---------- attention: bf16 HMMA, 128q CTA, 128k chunks, double-buffered ----------
#define PITCHB 144       // bytes per smem row (72 bf16)
#define BUFB   36864     // one buffer: K(18432) + V(18432)
__global__ void __launch_bounds__(256, 1) attn_mma() {
    extern __shared__ char smx[];
    unsigned smU = (unsigned)__cvta_generic_to_shared(smx);
    int w = blockIdx.y;
    int qb = blockIdx.x * 128;
    int t = threadIdx.x, warp = t >> 5, lane = t & 31;
    int g = lane >> 2, tig = lane & 3;
    const __nv_bfloat16* Qg = g_Qb + (size_t)w * 4096 * 64;
    const __nv_bfloat16* Vg = g_Vb + (size_t)w * 4096 * 64;

    // Q A-fragments, loaded once
    int q0 = qb + warp * 16;
    unsigned qa[4][4];
#pragma unroll
    for (int s = 0; s < 4; s++) {
        const __nv_bfloat16* bp = Qg + (q0 + g) * 64 + s * 16 + 2 * tig;
        qa[s][0] = *(const unsigned*)(bp);
        qa[s][1] = *(const unsigned*)(bp + 8 * 64);
        qa[s][2] = *(const unsigned*)(bp + 8);
        qa[s][3] = *(const unsigned*)(bp + 8 * 64 + 8);
    }

    float o[8][4];
#pragma unroll
    for (int i = 0; i < 8; i++)
#pragma unroll
        for (int jx = 0; jx < 4; jx++) o[i][jx] = 0.f;
    u64t rsA = 0ull, rsB = 0ull;                 // packed (0.f,0.f)

    int mi = lane >> 3, li = lane & 7;
    unsigned kOff = ((mi >> 1) * 8 + li) * PITCHB + (mi & 1) * 16;
    unsigned vOff = ((mi & 1) * 8 + li) * PITCHB + (mi >> 1) * 16;

    const u64t C18 = pk2(0.125f, 0.125f);
    const u64t K3 = pk2(0.1889038f, 0.1889038f);
    const u64t K2 = pk2(0.4964532f, 0.4964532f);
    const u64t K1 = pk2(1.0001804f, 1.0001804f);
    const u64t K0 = pk2(0.9999986f, 0.9999986f);

#define ISSUE(ch) do {                                                        \
        int _b = (ch) & 1;                                                    \
        unsigned _kd = smU + _b * BUFB, _vd = _kd + 18432;                    \
        const char* _ks = (const char*)(Qg + (ch) * 128 * 64);                \
        const char* _vs = (const char*)(Vg + (ch) * 128 * 64);                \
        _Pragma("unroll")                                                     \
        for (int _i = 0; _i < 4; _i++) {                                      \
            int _idx = t + _i * 256;                                          \
            int _r = _idx >> 3, _cg = _idx & 7;                               \
            unsigned _o = _r * PITCHB + _cg * 16;                             \
            unsigned _go = _r * 128 + _cg * 16;                               \
            cp16(_kd + _o, _ks + _go);                                        \
            cp16(_vd + _o, _vs + _go);                                        \
        }                                                                     \
        asm volatile("cp.async.commit_group;");                               \
    } while (0)

    ISSUE(0);
    ISSUE(1);

    for (int ch = 0; ch < 32; ch++) {
        if (ch < 31) asm volatile("cp.async.wait_group 1;");
        else         asm volatile("cp.async.wait_group 0;");
        __syncthreads();
        unsigned ksU = smU + (ch & 1) * BUFB;
        unsigned vsU = ksU + 18432;

        float p[16][4];
#pragma unroll
        for (int i = 0; i < 16; i++)
#pragma unroll
            for (int jx = 0; jx < 4; jx++) p[i][jx] = 0.f;

#pragma unroll
        for (int s = 0; s < 4; s++) {
#pragma unroll
            for (int jp = 0; jp < 8; jp++) {
                unsigned r0, r1, r2, r3;
                ldsm4(ksU + jp * (16 * PITCHB) + s * 32 + kOff, r0, r1, r2, r3);
                mma16816(p[2 * jp],     qa[s], r0, r1);
                mma16816(p[2 * jp + 1], qa[s], r2, r3);
            }
        }

        // exp (packed f32x2 cubic) + rowsum + pack to A-frags
        unsigned ea[8][4];
#pragma unroll
        for (int u = 0; u < 8; u++) {
            u64t d0 = pk2(p[2 * u][0],     p[2 * u][1]);
            u64t d1 = pk2(p[2 * u][2],     p[2 * u][3]);
            u64t d2 = pk2(p[2 * u + 1][0], p[2 * u + 1][1]);
            u64t d3 = pk2(p[2 * u + 1][2], p[2 * u + 1][3]);
            u64t s0 = fma2(d0, C18, C18), s1 = fma2(d1, C18, C18);
            u64t s2 = fma2(d2, C18, C18), s3 = fma2(d3, C18, C18);
            u64t e0 = fma2(s0, K3, K2); e0 = fma2(s0, e0, K1); e0 = fma2(s0, e0, K0);
            u64t e1 = fma2(s1, K3, K2); e1 = fma2(s1, e1, K1); e1 = fma2(s1, e1, K0);
            u64t e2 = fma2(s2, K3, K2); e2 = fma2(s2, e2, K1); e2 = fma2(s2, e2, K0);
            u64t e3 = fma2(s3, K3, K2); e3 = fma2(s3, e3, K1); e3 = fma2(s3, e3, K0);
            rsA = add2(rsA, e0); rsB = add2(rsB, e1);
            rsA = add2(rsA, e2); rsB = add2(rsB, e3);
            float f0, f1;
            upk2(e0, f0, f1); ea[u][0] = packbf(f0, f1);
            upk2(e1, f0, f1); ea[u][1] = packbf(f0, f1);
            upk2(e2, f0, f1); ea[u][2] = packbf(f0, f1);
            upk2(e3, f0, f1); ea[u][3] = packbf(f0, f1);
        }

        // O += P @ V
#pragma unroll
        for (int u = 0; u < 8; u++) {
#pragma unroll
            for (int cp = 0; cp < 4; cp++) {
                unsigned r0, r1, r2, r3;
                ldsm4t(vsU + u * (16 * PITCHB) + cp * 32 + vOff, r0, r1, r2, r3);
                mma16816(o[2 * cp],     ea[u], r0, r1);
                mma16816(o[2 * cp + 1], ea[u], r2, r3);
            }
        }
        __syncthreads();
        if (ch + 2 < 32) ISSUE(ch + 2);
    }

    float rs0a, rs0b, rs1a, rs1b;
    upk2(rsA, rs0a, rs0b); upk2(rsB, rs1a, rs1b);
    float rs0 = rs0a + rs0b, rs1 = rs1a + rs1b;
    rs0 += __shfl_xor_sync(0xFFFFFFFFu, rs0, 1);
    rs0 += __shfl_xor_sync(0xFFFFFFFFu, rs0, 2);
    rs1 += __shfl_xor_sync(0xFFFFFFFFu, rs1, 1);
    rs1 += __shfl_xor_sync(0xFFFFFFFFu, rs1, 2);
    float i0 = 1.f / rs0, i1 = 1.f / rs1;

    float* outp = g_attn + (size_t)(w * 4096 + q0) * 64;
#pragma unroll
    for (int c = 0; c < 8; c++) {
        int col = c * 8 + 2 * tig;
        *(float2*)(outp + g * 64 + col)       = make_float2(o[c][0] * i0, o[c][1] * i0);
        *(float2*)(outp + (g + 8) * 64 + col) = make_float2(o[c][2] * i1, o[c][3] * i1);
    }
}

// ---------- fused 1x1 conv (attn 64ch + unet 1ch) + bias + residual -> g_t ----------
__global__ void convl_fused(const float* __restrict__ unet, const float* __restrict__ x,
                            const float* __restrict__ bias) {
    __shared__ float w_s[4160];
    int t = threadIdx.x;
    for (int i = t; i < 4160; i += 256) w_s[i] = g_wlT[i];
    __syncthreads();
    int p = blockIdx.x * 128 + (t & 127);
    int cog = t >> 7;
    float acc[32];
#pragma unroll
    for (int i = 0; i < 32; i++) acc[i] = 0.f;
    for (int ci = 0; ci < 65; ci++) {
        float v = (ci < 64) ? g_attn[ci * 16384 + p] : unet[p];
        const float4* wr = (const float4*)(w_s + ci * 64 + cog * 32);
#pragma unroll
        for (int k = 0; k < 8; k++) {
            float4 wv = wr[k];
            acc[4 * k + 0] = fmaf(wv.x, v, acc[4 * k + 0]);
            acc[4 * k + 1] = fmaf(wv.y, v, acc[4 * k + 1]);
            acc[4 * k + 2] = fmaf(wv.z, v, acc[4 * k + 2]);
            acc[4 * k + 3] = fmaf(wv.w, v, acc[4 * k + 3]);
        }
    }
#pragma unroll
    for (int i = 0; i < 32; i++) {
        int co = cog * 32 + i;
        g_t[co * 16384 + p] = x[co * 16384 + p] + acc[i] + bias[co];
    }
}

// ---------- tiled 3x3 conv (dilation D) + relu, f32x2 ----------
template <int D>
__global__ void conv3x3(const float* __restrict__ in, const float* __restrict__ wT,
                        const float* __restrict__ bias, float* __restrict__ out) {
    constexpr int IH = 8 + 2 * D, IW = 16 + 2 * D;
    __shared__ float in_s[8 * IH * IW];
    __shared__ float w_s[8 * 9 * 64];
    int t = threadIdx.x;
    int co8 = (t & 7) * 8;          // 8 consecutive output channels
    int pxg = t >> 3;               // 0..31, 4 consecutive pixels each
    int r = pxg >> 2, cbase = (pxg & 3) * 4;
    int r0 = blockIdx.y * 8, c0 = blockIdx.x * 16;

    u64t acc[4][4];                 // [px][co-pair]
#pragma unroll
    for (int j = 0; j < 4; j++) {
        u64t b2 = *(const u64t*)(bias + co8 + 2 * j);
#pragma unroll
        for (int i = 0; i < 4; i++) acc[i][j] = b2;
    }

    for (int cib = 0; cib < 64; cib += 8) {
        __syncthreads();
        for (int idx = t; idx < 8 * IH * IW; idx += 256) {
            int ci = idx / (IH * IW), rem = idx - ci * (IH * IW);
            int rr = rem / IW, cc = rem - rr * IW;
            int gr = r0 - D + rr, gc = c0 - D + cc;
            float v = 0.f;
            if (gr >= 0 && gr < 128 && gc >= 0 && gc < 128)
                v = in[(cib + ci) * 16384 + gr * 128 + gc];
            in_s[idx] = v;
        }
        for (int idx = t; idx < 8 * 576; idx += 256) w_s[idx] = wT[cib * 576 + idx];
        __syncthreads();
#pragma unroll
        for (int ci = 0; ci < 8; ci++) {
#pragma unroll
            for (int kh = 0; kh < 3; kh++) {
#pragma unroll
                for (int kw = 0; kw < 3; kw++) {
                    const float* ip = &in_s[ci * IH * IW + (r + kh * D) * IW + cbase + kw * D];
                    u64t v0 = pk2(ip[0], ip[0]);
                    u64t v1 = pk2(ip[1], ip[1]);
                    u64t v2 = pk2(ip[2], ip[2]);
                    u64t v3 = pk2(ip[3], ip[3]);
                    const u64t* wr = (const u64t*)(w_s + (ci * 9 + kh * 3 + kw) * 64 + co8);
#pragma unroll
                    for (int j = 0; j < 4; j++) {
                        u64t w2 = wr[j];
                        acc[0][j] = fma2(v0, w2, acc[0][j]);
                        acc[1][j] = fma2(v1, w2, acc[1][j]);
                        acc[2][j] = fma2(v2, w2, acc[2][j]);
                        acc[3][j] = fma2(v3, w2, acc[3][j]);
                    }
                }
            }
        }
    }
    int gp0 = (r0 + r) * 128 + c0 + cbase;
#pragma unroll
    for (int i = 0; i < 4; i++) {
#pragma unroll
        for (int j = 0; j < 4; j++) {
            float a, bb;
            upk2(acc[i][j], a, bb);
            out[(co8 + 2 * j) * 16384 + gp0 + i]     = fmaxf(a, 0.f);
            out[(co8 + 2 * j + 1) * 16384 + gp0 + i] = fmaxf(bb, 0.f);
        }
    }
}

// ---------- final 1x1 conv + bias + residual -> d_out ----------
__global__ void conv1x1_final(const float* __restrict__ x, const float* __restrict__ bias,
                              float* __restrict__ out) {
    __shared__ float w_s[4096];
    int t = threadIdx.x;
    for (int i = t; i < 4096; i += 256) w_s[i] = g_w3T[i];
    __syncthreads();
    int p = blockIdx.x * 128 + (t & 127);
    int cog = t >> 7;
    float acc[32];
#pragma unroll
    for (int i = 0; i < 32; i++) acc[i] = 0.f;
    for (int ci = 0; ci < 64; ci++) {
        float v = g_z2[ci * 16384 + p];
        const float4* wr = (const float4*)(w_s + ci * 64 + cog * 32);
#pragma unroll
        for (int k = 0; k < 8; k++) {
            float4 wv = wr[k];
            acc[4 * k + 0] = fmaf(wv.x, v, acc[4 * k + 0]);
            acc[4 * k + 1] = fmaf(wv.y, v, acc[4 * k + 1]);
            acc[4 * k + 2] = fmaf(wv.z, v, acc[4 * k + 2]);
            acc[4 * k + 3] = fmaf(wv.w, v, acc[4 * k + 3]);
        }
    }
#pragma unroll
    for (int i = 0; i < 32; i++) {
        int co = cog * 32 + i;
        out[co * 16384 + p] = x[co * 16384 + p] + acc[i] + bias[co];
    }
}

extern "C" void kernel_launch(void* const* d_in, const int* in_sizes, int n_in,
                              void* d_out, int out_size) {
    const float* x     = (const float*)d_in[0];
    const float* unet  = (const float*)d_in[1];
    const float* wqk   = (const float*)d_in[2];
    const float* c1w   = (const float*)d_in[3];
    const float* c1b   = (const float*)d_in[4];
    const float* c2w   = (const float*)d_in[5];
    const float* c2b   = (const float*)d_in[6];
    const float* c3w   = (const float*)d_in[7];
    const float* c3b   = (const float*)d_in[8];
    const float* clw   = (const float*)d_in[9];
    const float* clb   = (const float*)d_in[10];
    float* out = (float*)d_out;

    static bool attr_set = false;
    if (!attr_set) {
        cudaFuncSetAttribute(attn_mma, cudaFuncAttributeMaxDynamicSharedMemorySize, 2 * BUFB);
        attr_set = true;
    }

    prep_w<<<144, 256>>>(c1w, c2w, c3w, clw);
    mean1<<<128, 256>>>(x);
    mean2<<<1, 128>>>(wqk);
    qv_build<<<512, 256>>>(x, wqk);
    attn_mma<<<dim3(32, 4), 256, 2 * BUFB>>>();
    convl_fused<<<128, 256>>>(unet, x, clb);
    float* z1; cudaGetSymbolAddress((void**)&z1, g_z1);
    float* z2; cudaGetSymbolAddress((void**)&z2, g_z2);
    float* tt; cudaGetSymbolAddress((void**)&tt, g_t);
    float* w1T; cudaGetSymbolAddress((void**)&w1T, g_w1T);
    float* w2T; cudaGetSymbolAddress((void**)&w2T, g_w2T);
    conv3x3<1><<<dim3(8, 16), 256>>>(tt, w1T, c1b, z1);
    conv3x3<2><<<dim3(8, 16), 256>>>(z1, w2T, c2b, z2);
    conv1x1_final<<<128, 256>>>(x, c3b, out);
}

// round 6
// speedup vs baseline: 2.5701x; 1.0074x over previous
#include <cuda_runtime.h>
#include <cuda_bf16.h>

typedef unsigned long long u64t;

// ---------- scratch ----------
__device__ float g_part[128];
__device__ float g_mvec[64];
__device__ __align__(16) __nv_bfloat16 g_Qb[4 * 4096 * 64]; // [w][n][d] normalized Q (=K)
__device__ __align__(16) __nv_bfloat16 g_Vb[4 * 4096 * 64]; // [w][n][c]
__device__ float g_attn[1048576];                           // raw reshape (64,128,128)
__device__ float g_t [1048576];
__device__ float g_z1[1048576];
__device__ float g_z2[1048576];
__device__ float g_w1T[64 * 9 * 64];
__device__ float g_w2T[64 * 9 * 64];
__device__ float g_w3T[64 * 64];
__device__ float g_wlT[65 * 64];

// ---------- f32x2 helpers ----------
__device__ __forceinline__ u64t pk2(float a, float b) {
    u64t r; asm("mov.b64 %0,{%1,%2};" : "=l"(r) : "f"(a), "f"(b)); return r;
}
__device__ __forceinline__ void upk2(u64t v, float& a, float& b) {
    asm("mov.b64 {%0,%1},%2;" : "=f"(a), "=f"(b) : "l"(v));
}
__device__ __forceinline__ u64t fma2(u64t a, u64t b, u64t c) {
    u64t d; asm("fma.rn.f32x2 %0,%1,%2,%3;" : "=l"(d) : "l"(a), "l"(b), "l"(c)); return d;
}
__device__ __forceinline__ u64t add2(u64t a, u64t b) {
    u64t d; asm("add.rn.f32x2 %0,%1,%2;" : "=l"(d) : "l"(a), "l"(b)); return d;
}

// ---------- stage 1 of global mean ----------
__global__ void mean1(const float* __restrict__ x) {
    __shared__ float red[256];
    int t = threadIdx.x;
    int base = blockIdx.x * 8192;
    float s = 0.f;
#pragma unroll
    for (int k = 0; k < 32; k++) s += x[base + k * 256 + t];
    red[t] = s; __syncthreads();
    for (int o = 128; o; o >>= 1) { if (t < o) red[t] += red[t + o]; __syncthreads(); }
    if (t == 0) g_part[blockIdx.x] = red[0];
}

// ---------- weight transposes + mean stage 2 (merged) ----------
__global__ void prep_w2(const float* __restrict__ w1, const float* __restrict__ w2,
                        const float* __restrict__ w3, const float* __restrict__ wl,
                        const float* __restrict__ wqk) {
    int t = threadIdx.x;
    int i = blockIdx.x * 256 + t;
    {
        int co = i / 576, r = i - co * 576;
        g_w1T[r * 64 + co] = w1[i];
        g_w2T[r * 64 + co] = w2[i];
    }
    if (i < 4096) { int co = i >> 6, ci = i & 63; g_w3T[ci * 64 + co] = w3[i]; }
    if (i < 4160) { int co = i / 65, ci = i - co * 65; g_wlT[ci * 64 + co] = wl[i]; }
    if (blockIdx.x == 0) {
        __shared__ float red[128];
        __shared__ float m_sh;
        if (t < 128) red[t] = g_part[t];
        __syncthreads();
        for (int o = 64; o; o >>= 1) { if (t < o) red[t] += red[t + o]; __syncthreads(); }
        if (t == 0) m_sh = red[0] * (1.0f / 1048576.0f);
        __syncthreads();
        if (t < 64) {
            float cs = 0.f;
            for (int c = 0; c < 64; c++) cs += wqk[c * 64 + t];
            g_mvec[t] = m_sh * cs;
        }
    }
}

// ---------- build normalized Q (bf16) and V (bf16); warp-per-row ----------
__global__ void qv_build(const float* __restrict__ x, const float* __restrict__ wqk) {
    __shared__ float wqk_s[4096];
    __shared__ float xs[32 * 65];
    int b = blockIdx.x;                 // 512 blocks
    int w = b >> 7, rb = b & 127;
    int hs = rb >> 1, wsb = (rb & 1) * 32;
    int dh = w >> 1, dw = w & 1;
    int t = threadIdx.x;
    for (int i = t; i < 4096; i += 256) wqk_s[i] = wqk[i];
    int h = 2 * hs + dh;
    for (int i = t; i < 2048; i += 256) {
        int c = i >> 5, j = i & 31;
        int wp = 2 * (wsb + j) + dw;
        xs[j * 65 + c] = x[c * 16384 + h * 128 + wp];
    }
    __syncthreads();
    int nbase = hs * 64 + wsb;
    for (int i = t; i < 2048; i += 256) {           // V bf16
        int c = i & 63, j = i >> 6;
        g_Vb[(w * 4096 + nbase + j) * 64 + c] = __float2bfloat16(xs[j * 65 + c]);
    }
    int lane = t & 31, warp = t >> 5;
    float mv0 = g_mvec[lane], mv1 = g_mvec[lane + 32];
#pragma unroll
    for (int k = 0; k < 4; k++) {
        int jj = warp + 8 * k;
        float u0 = 0.f, u1 = 0.f;
#pragma unroll 8
        for (int c = 0; c < 64; c++) {
            float xv = xs[jj * 65 + c];
            u0 = fmaf(xv, wqk_s[c * 64 + lane], u0);
            u1 = fmaf(xv, wqk_s[c * 64 + lane + 32], u1);
        }
        u0 -= mv0; u1 -= mv1;
        float ss = u0 * u0 + u1 * u1;
#pragma unroll
        for (int o = 16; o; o >>= 1) ss += __shfl_xor_sync(0xFFFFFFFFu, ss, o);
        float rinv = rsqrtf(ss + 1e-24f);
        __nv_bfloat16* qp = g_Qb + (size_t)(w * 4096 + nbase + jj) * 64;
        qp[lane] = __float2bfloat16(u0 * rinv);
        qp[lane + 32] = __float2bfloat16(u1 * rinv);
    }
}

// ---------- mma helpers ----------
__device__ __forceinline__ void ldsm4(unsigned addr, unsigned& r0, unsigned& r1,
                                      unsigned& r2, unsigned& r3) {
    asm volatile("ldmatrix.sync.aligned.m8n8.x4.shared.b16 {%0,%1,%2,%3}, [%4];"
                 : "=r"(r0), "=r"(r1), "=r"(r2), "=r"(r3) : "r"(addr));
}
__device__ __forceinline__ void ldsm4t(unsigned addr, unsigned& r0, unsigned& r1,
                                       unsigned& r2, unsigned& r3) {
    asm volatile("ldmatrix.sync.aligned.m8n8.x4.trans.shared.b16 {%0,%1,%2,%3}, [%4];"
                 : "=r"(r0), "=r"(r1), "=r"(r2), "=r"(r3) : "r"(addr));
}
__device__ __forceinline__ void mma16816(float* c, const unsigned* a, unsigned b0, unsigned b1) {
    asm volatile("mma.sync.aligned.m16n8k16.row.col.f32.bf16.bf16.f32 "
                 "{%0,%1,%2,%3},{%4,%5,%6,%7},{%8,%9},{%0,%1,%2,%3};"
                 : "+f"(c[0]), "+f"(c[1]), "+f"(c[2]), "+f"(c[3])
                 : "r"(a[0]), "r"(a[1]), "r"(a[2]), "r"(a[3]), "r"(b0), "r"(b1));
}
__device__ __forceinline__ unsigned packbf(float lo, float hi) {
    __nv_bfloat162 h = __floats2bfloat162_rn(lo, hi);
    return *(unsigned*)&h;
}
__device__ __forceinline__ void cp16(unsigned dst, const void* src) {
    asm volatile("cp.async.cg.shared.global [%0], [%1], 16;" :: "r"(dst), "l"(src));
}

// ---------- attention: bf16 HMMA, jp-pipelined (low regs), double-buffered ----------
#define PITCHB 144       // bytes per smem row (72 bf16)
#define BUFB   36864     // one buffer: K(18432) + V(18432)
__global__ void __launch_bounds__(256, 1) attn_mma() {
    extern __shared__ char smx[];
    unsigned smU = (unsigned)__cvta_generic_to_shared(smx);
    int w = blockIdx.y;
    int qb = blockIdx.x * 128;
    int t = threadIdx.x, warp = t >> 5, lane = t & 31;
    int g = lane >> 2, tig = lane & 3;
    const __nv_bfloat16* Qg = g_Qb + (size_t)w * 4096 * 64;
    const __nv_bfloat16* Vg = g_Vb + (size_t)w * 4096 * 64;

    // Q A-fragments, loaded once
    int q0 = qb + warp * 16;
    unsigned qa[4][4];
#pragma unroll
    for (int s = 0; s < 4; s++) {
        const __nv_bfloat16* bp = Qg + (q0 + g) * 64 + s * 16 + 2 * tig;
        qa[s][0] = *(const unsigned*)(bp);
        qa[s][1] = *(const unsigned*)(bp + 8 * 64);
        qa[s][2] = *(const unsigned*)(bp + 8);
        qa[s][3] = *(const unsigned*)(bp + 8 * 64 + 8);
    }

    float o[8][4];
#pragma unroll
    for (int i = 0; i < 8; i++)
#pragma unroll
        for (int jx = 0; jx < 4; jx++) o[i][jx] = 0.f;
    u64t rsA = 0ull, rsB = 0ull;

    int mi = lane >> 3, li = lane & 7;
    unsigned kOff = ((mi >> 1) * 8 + li) * PITCHB + (mi & 1) * 16;
    unsigned vOff = ((mi & 1) * 8 + li) * PITCHB + (mi >> 1) * 16;

    const u64t C18 = pk2(0.125f, 0.125f);
    const u64t K3 = pk2(0.1889038f, 0.1889038f);
    const u64t K2 = pk2(0.4964532f, 0.4964532f);
    const u64t K1 = pk2(1.0001804f, 1.0001804f);
    const u64t K0 = pk2(0.9999986f, 0.9999986f);

#define ISSUE(ch) do {                                                        \
        int _b = (ch) & 1;                                                    \
        unsigned _kd = smU + _b * BUFB, _vd = _kd + 18432;                    \
        const char* _ks = (const char*)(Qg + (ch) * 128 * 64);                \
        const char* _vs = (const char*)(Vg + (ch) * 128 * 64);                \
        _Pragma("unroll")                                                     \
        for (int _i = 0; _i < 4; _i++) {                                      \
            int _idx = t + _i * 256;                                          \
            int _r = _idx >> 3, _cg = _idx & 7;                               \
            unsigned _o = _r * PITCHB + _cg * 16;                             \
            unsigned _go = _r * 128 + _cg * 16;                               \
            cp16(_kd + _o, _ks + _go);                                        \
            cp16(_vd + _o, _vs + _go);                                        \
        }                                                                     \
        asm volatile("cp.async.commit_group;");                               \
    } while (0)

    ISSUE(0);
    ISSUE(1);

    for (int ch = 0; ch < 32; ch++) {
        if (ch < 31) asm volatile("cp.async.wait_group 1;");
        else         asm volatile("cp.async.wait_group 0;");
        __syncthreads();
        unsigned ksU = smU + (ch & 1) * BUFB;
        unsigned vsU = ksU + 18432;

#pragma unroll
        for (int jp = 0; jp < 8; jp++) {
            // --- QK^T for k-sub-block jp (16 k-cols) ---
            float p0[4] = {0.f, 0.f, 0.f, 0.f};
            float p1[4] = {0.f, 0.f, 0.f, 0.f};
#pragma unroll
            for (int s = 0; s < 4; s++) {
                unsigned r0, r1, r2, r3;
                ldsm4(ksU + jp * (16 * PITCHB) + s * 32 + kOff, r0, r1, r2, r3);
                mma16816(p0, qa[s], r0, r1);
                mma16816(p1, qa[s], r2, r3);
            }
            // --- exp (packed f32x2 cubic) + rowsum + pack ---
            u64t d0 = pk2(p0[0], p0[1]);
            u64t d1 = pk2(p0[2], p0[3]);
            u64t d2 = pk2(p1[0], p1[1]);
            u64t d3 = pk2(p1[2], p1[3]);
            u64t s0 = fma2(d0, C18, C18), s1 = fma2(d1, C18, C18);
            u64t s2 = fma2(d2, C18, C18), s3 = fma2(d3, C18, C18);
            u64t e0 = fma2(s0, K3, K2); e0 = fma2(s0, e0, K1); e0 = fma2(s0, e0, K0);
            u64t e1 = fma2(s1, K3, K2); e1 = fma2(s1, e1, K1); e1 = fma2(s1, e1, K0);
            u64t e2 = fma2(s2, K3, K2); e2 = fma2(s2, e2, K1); e2 = fma2(s2, e2, K0);
            u64t e3 = fma2(s3, K3, K2); e3 = fma2(s3, e3, K1); e3 = fma2(s3, e3, K0);
            rsA = add2(rsA, e0); rsB = add2(rsB, e1);
            rsA = add2(rsA, e2); rsB = add2(rsB, e3);
            unsigned ea[4];
            float f0, f1;
            upk2(e0, f0, f1); ea[0] = packbf(f0, f1);
            upk2(e1, f0, f1); ea[1] = packbf(f0, f1);
            upk2(e2, f0, f1); ea[2] = packbf(f0, f1);
            upk2(e3, f0, f1); ea[3] = packbf(f0, f1);
            // --- PV for the same k-sub-block (V rows jp*16..) ---
#pragma unroll
            for (int cp = 0; cp < 4; cp++) {
                unsigned r0, r1, r2, r3;
                ldsm4t(vsU + jp * (16 * PITCHB) + cp * 32 + vOff, r0, r1, r2, r3);
                mma16816(o[2 * cp],     ea, r0, r1);
                mma16816(o[2 * cp + 1], ea, r2, r3);
            }
        }
        __syncthreads();
        if (ch + 2 < 32) ISSUE(ch + 2);
    }

    float rs0a, rs0b, rs1a, rs1b;
    upk2(rsA, rs0a, rs0b); upk2(rsB, rs1a, rs1b);
    float rs0 = rs0a + rs0b, rs1 = rs1a + rs1b;
    rs0 += __shfl_xor_sync(0xFFFFFFFFu, rs0, 1);
    rs0 += __shfl_xor_sync(0xFFFFFFFFu, rs0, 2);
    rs1 += __shfl_xor_sync(0xFFFFFFFFu, rs1, 1);
    rs1 += __shfl_xor_sync(0xFFFFFFFFu, rs1, 2);
    float i0 = 1.f / rs0, i1 = 1.f / rs1;

    float* outp = g_attn + (size_t)(w * 4096 + q0) * 64;
#pragma unroll
    for (int c = 0; c < 8; c++) {
        int col = c * 8 + 2 * tig;
        *(float2*)(outp + g * 64 + col)       = make_float2(o[c][0] * i0, o[c][1] * i0);
        *(float2*)(outp + (g + 8) * 64 + col) = make_float2(o[c][2] * i1, o[c][3] * i1);
    }
}

// ---------- fused 1x1 conv (attn 64ch + unet 1ch) + bias + residual -> g_t ----------
__global__ void convl_fused(const float* __restrict__ unet, const float* __restrict__ x,
                            const float* __restrict__ bias) {
    __shared__ float w_s[4160];
    int t = threadIdx.x;
    for (int i = t; i < 4160; i += 256) w_s[i] = g_wlT[i];
    __syncthreads();
    int p = blockIdx.x * 128 + (t & 127);
    int cog = t >> 7;
    float acc[32];
#pragma unroll
    for (int i = 0; i < 32; i++) acc[i] = 0.f;
    for (int ci = 0; ci < 65; ci++) {
        float v = (ci < 64) ? g_attn[ci * 16384 + p] : unet[p];
        const float4* wr = (const float4*)(w_s + ci * 64 + cog * 32);
#pragma unroll
        for (int k = 0; k < 8; k++) {
            float4 wv = wr[k];
            acc[4 * k + 0] = fmaf(wv.x, v, acc[4 * k + 0]);
            acc[4 * k + 1] = fmaf(wv.y, v, acc[4 * k + 1]);
            acc[4 * k + 2] = fmaf(wv.z, v, acc[4 * k + 2]);
            acc[4 * k + 3] = fmaf(wv.w, v, acc[4 * k + 3]);
        }
    }
#pragma unroll
    for (int i = 0; i < 32; i++) {
        int co = cog * 32 + i;
        g_t[co * 16384 + p] = x[co * 16384 + p] + acc[i] + bias[co];
    }
}

// ---------- tiled 3x3 conv (dilation D) + relu, f32x2 ----------
template <int D>
__global__ void conv3x3(const float* __restrict__ in, const float* __restrict__ wT,
                        const float* __restrict__ bias, float* __restrict__ out) {
    constexpr int IH = 8 + 2 * D, IW = 16 + 2 * D;
    __shared__ float in_s[8 * IH * IW];
    __shared__ float w_s[8 * 9 * 64];
    int t = threadIdx.x;
    int co8 = (t & 7) * 8;
    int pxg = t >> 3;
    int r = pxg >> 2, cbase = (pxg & 3) * 4;
    int r0 = blockIdx.y * 8, c0 = blockIdx.x * 16;

    u64t acc[4][4];
#pragma unroll
    for (int j = 0; j < 4; j++) {
        u64t b2 = *(const u64t*)(bias + co8 + 2 * j);
#pragma unroll
        for (int i = 0; i < 4; i++) acc[i][j] = b2;
    }

    for (int cib = 0; cib < 64; cib += 8) {
        __syncthreads();
        for (int idx = t; idx < 8 * IH * IW; idx += 256) {
            int ci = idx / (IH * IW), rem = idx - ci * (IH * IW);
            int rr = rem / IW, cc = rem - rr * IW;
            int gr = r0 - D + rr, gc = c0 - D + cc;
            float v = 0.f;
            if (gr >= 0 && gr < 128 && gc >= 0 && gc < 128)
                v = in[(cib + ci) * 16384 + gr * 128 + gc];
            in_s[idx] = v;
        }
        for (int idx = t; idx < 8 * 576; idx += 256) w_s[idx] = wT[cib * 576 + idx];
        __syncthreads();
#pragma unroll
        for (int ci = 0; ci < 8; ci++) {
#pragma unroll
            for (int kh = 0; kh < 3; kh++) {
#pragma unroll
                for (int kw = 0; kw < 3; kw++) {
                    const float* ip = &in_s[ci * IH * IW + (r + kh * D) * IW + cbase + kw * D];
                    u64t v0 = pk2(ip[0], ip[0]);
                    u64t v1 = pk2(ip[1], ip[1]);
                    u64t v2 = pk2(ip[2], ip[2]);
                    u64t v3 = pk2(ip[3], ip[3]);
                    const u64t* wr = (const u64t*)(w_s + (ci * 9 + kh * 3 + kw) * 64 + co8);
#pragma unroll
                    for (int j = 0; j < 4; j++) {
                        u64t w2 = wr[j];
                        acc[0][j] = fma2(v0, w2, acc[0][j]);
                        acc[1][j] = fma2(v1, w2, acc[1][j]);
                        acc[2][j] = fma2(v2, w2, acc[2][j]);
                        acc[3][j] = fma2(v3, w2, acc[3][j]);
                    }
                }
            }
        }
    }
    int gp0 = (r0 + r) * 128 + c0 + cbase;
#pragma unroll
    for (int i = 0; i < 4; i++) {
#pragma unroll
        for (int j = 0; j < 4; j++) {
            float a, bb;
            upk2(acc[i][j], a, bb);
            out[(co8 + 2 * j) * 16384 + gp0 + i]     = fmaxf(a, 0.f);
            out[(co8 + 2 * j + 1) * 16384 + gp0 + i] = fmaxf(bb, 0.f);
        }
    }
}

// ---------- final 1x1 conv + bias + residual -> d_out ----------
__global__ void conv1x1_final(const float* __restrict__ x, const float* __restrict__ bias,
                              float* __restrict__ out) {
    __shared__ float w_s[4096];
    int t = threadIdx.x;
    for (int i = t; i < 4096; i += 256) w_s[i] = g_w3T[i];
    __syncthreads();
    int p = blockIdx.x * 128 + (t & 127);
    int cog = t >> 7;
    float acc[32];
#pragma unroll
    for (int i = 0; i < 32; i++) acc[i] = 0.f;
    for (int ci = 0; ci < 64; ci++) {
        float v = g_z2[ci * 16384 + p];
        const float4* wr = (const float4*)(w_s + ci * 64 + cog * 32);
#pragma unroll
        for (int k = 0; k < 8; k++) {
            float4 wv = wr[k];
            acc[4 * k + 0] = fmaf(wv.x, v, acc[4 * k + 0]);
            acc[4 * k + 1] = fmaf(wv.y, v, acc[4 * k + 1]);
            acc[4 * k + 2] = fmaf(wv.z, v, acc[4 * k + 2]);
            acc[4 * k + 3] = fmaf(wv.w, v, acc[4 * k + 3]);
        }
    }
#pragma unroll
    for (int i = 0; i < 32; i++) {
        int co = cog * 32 + i;
        out[co * 16384 + p] = x[co * 16384 + p] + acc[i] + bias[co];
    }
}

extern "C" void kernel_launch(void* const* d_in, const int* in_sizes, int n_in,
                              void* d_out, int out_size) {
    const float* x     = (const float*)d_in[0];
    const float* unet  = (const float*)d_in[1];
    const float* wqk   = (const float*)d_in[2];
    const float* c1w   = (const float*)d_in[3];
    const float* c1b   = (const float*)d_in[4];
    const float* c2w   = (const float*)d_in[5];
    const float* c2b   = (const float*)d_in[6];
    const float* c3w   = (const float*)d_in[7];
    const float* c3b   = (const float*)d_in[8];
    const float* clw   = (const float*)d_in[9];
    const float* clb   = (const float*)d_in[10];
    float* out = (float*)d_out;

    cudaFuncSetAttribute(attn_mma, cudaFuncAttributeMaxDynamicSharedMemorySize, 2 * BUFB);

    mean1<<<128, 256>>>(x);
    prep_w2<<<144, 256>>>(c1w, c2w, c3w, clw, wqk);
    qv_build<<<512, 256>>>(x, wqk);
    attn_mma<<<dim3(32, 4), 256, 2 * BUFB>>>();
    convl_fused<<<128, 256>>>(unet, x, clb);
    float* z1; cudaGetSymbolAddress((void**)&z1, g_z1);
    float* z2; cudaGetSymbolAddress((void**)&z2, g_z2);
    float* tt; cudaGetSymbolAddress((void**)&tt, g_t);
    float* w1T; cudaGetSymbolAddress((void**)&w1T, g_w1T);
    float* w2T; cudaGetSymbolAddress((void**)&w2T, g_w2T);
    conv3x3<1><<<dim3(8, 16), 256>>>(tt, w1T, c1b, z1);
    conv3x3<2><<<dim3(8, 16), 256>>>(z1, w2T, c2b, z2);
    conv1x1_final<<<128, 256>>>(x, c3b, out);
}

// round 7
// speedup vs baseline: 3.5439x; 1.3789x over previous
#include <cuda_runtime.h>
#include <cuda_bf16.h>

typedef unsigned long long u64t;

// ---------- scratch ----------
__device__ float g_part[128];
__device__ float g_mvec[64];
__device__ __align__(16) __nv_bfloat16 g_Qb[4 * 4096 * 64]; // [w][n][d] normalized Q (=K)
__device__ __align__(16) __nv_bfloat16 g_Vb[4 * 4096 * 64]; // [w][n][c]
__device__ float g_attn[1048576];                           // raw reshape (64,128,128)
__device__ float g_t [1048576];
__device__ float g_z1[1048576];
__device__ float g_z2[1048576];
__device__ float g_wc1[36864];   // tf32 weights, [co][ci*9+tap] (same order as input)
__device__ float g_wc2[36864];
__device__ float g_w3T[64 * 64];
__device__ float g_wlT[65 * 64];

// ---------- f32x2 helpers ----------
__device__ __forceinline__ u64t pk2(float a, float b) {
    u64t r; asm("mov.b64 %0,{%1,%2};" : "=l"(r) : "f"(a), "f"(b)); return r;
}
__device__ __forceinline__ void upk2(u64t v, float& a, float& b) {
    asm("mov.b64 {%0,%1},%2;" : "=f"(a), "=f"(b) : "l"(v));
}
__device__ __forceinline__ u64t fma2(u64t a, u64t b, u64t c) {
    u64t d; asm("fma.rn.f32x2 %0,%1,%2,%3;" : "=l"(d) : "l"(a), "l"(b), "l"(c)); return d;
}
__device__ __forceinline__ u64t add2(u64t a, u64t b) {
    u64t d; asm("add.rn.f32x2 %0,%1,%2;" : "=l"(d) : "l"(a), "l"(b)); return d;
}
__device__ __forceinline__ unsigned cvt_tf32(float f) {
    unsigned u; asm("cvt.rna.tf32.f32 %0,%1;" : "=r"(u) : "f"(f)); return u;
}

// ---------- stage 1 of global mean ----------
__global__ void mean1(const float* __restrict__ x) {
    __shared__ float red[256];
    int t = threadIdx.x;
    int base = blockIdx.x * 8192;
    float s = 0.f;
#pragma unroll
    for (int k = 0; k < 32; k++) s += x[base + k * 256 + t];
    red[t] = s; __syncthreads();
    for (int o = 128; o; o >>= 1) { if (t < o) red[t] += red[t + o]; __syncthreads(); }
    if (t == 0) g_part[blockIdx.x] = red[0];
}

// ---------- weight prep (tf32 convs + fp32 1x1 transposes) + mean stage 2 ----------
__global__ void prep_w2(const float* __restrict__ w1, const float* __restrict__ w2,
                        const float* __restrict__ w3, const float* __restrict__ wl,
                        const float* __restrict__ wqk) {
    int t = threadIdx.x;
    int i = blockIdx.x * 256 + t;          // 144 blocks -> [0,36864)
    g_wc1[i] = __uint_as_float(cvt_tf32(w1[i]));
    g_wc2[i] = __uint_as_float(cvt_tf32(w2[i]));
    if (i < 4096) { int co = i >> 6, ci = i & 63; g_w3T[ci * 64 + co] = w3[i]; }
    if (i < 4160) { int co = i / 65, ci = i - co * 65; g_wlT[ci * 64 + co] = wl[i]; }
    if (blockIdx.x == 0) {
        __shared__ float red[128];
        __shared__ float m_sh;
        if (t < 128) red[t] = g_part[t];
        __syncthreads();
        for (int o = 64; o; o >>= 1) { if (t < o) red[t] += red[t + o]; __syncthreads(); }
        if (t == 0) m_sh = red[0] * (1.0f / 1048576.0f);
        __syncthreads();
        if (t < 64) {
            float cs = 0.f;
            for (int c = 0; c < 64; c++) cs += wqk[c * 64 + t];
            g_mvec[t] = m_sh * cs;
        }
    }
}

// ---------- build normalized Q (bf16) and V (bf16); 16 rows/block ----------
__global__ void __launch_bounds__(256) qv_build(const float* __restrict__ x,
                                                const float* __restrict__ wqk) {
    __shared__ float wT[64 * 66];   // [e][c] pitch 66
    __shared__ float xs[16 * 66];   // [j][c] pitch 66
    int b = blockIdx.x;             // 1024 blocks
    int w = b >> 8, rb = b & 255;
    int hs = rb >> 2, ws0 = (rb & 3) * 16;
    int dh = w >> 1, dw = w & 1;
    int t = threadIdx.x;
    int h = 2 * hs + dh;
    for (int i = t; i < 4096; i += 256)
        wT[(i & 63) * 66 + (i >> 6)] = wqk[i];
#pragma unroll
    for (int pass = 0; pass < 4; pass++) {
        int i = pass * 256 + t;
        int j = i & 15, c = i >> 4;
        xs[j * 66 + c] = x[c * 16384 + h * 128 + 2 * (ws0 + j) + dw];
    }
    __syncthreads();
    int nbase = hs * 64 + ws0;
#pragma unroll
    for (int pass = 0; pass < 4; pass++) {       // V bf16
        int i = pass * 256 + t;
        int c = i & 63, j = i >> 6;
        g_Vb[(w * 4096 + nbase + j) * 64 + c] = __float2bfloat16(xs[j * 66 + c]);
    }
    int lane = t & 31, warp = t >> 5;
    int j0 = warp * 2, j1 = j0 + 1;
    float mv0 = g_mvec[lane], mv1 = g_mvec[lane + 32];
    float u00 = 0.f, u01 = 0.f, u10 = 0.f, u11 = 0.f;
    const float2* w0p = (const float2*)(wT + lane * 66);
    const float2* w1p = (const float2*)(wT + (lane + 32) * 66);
    const float2* x0p = (const float2*)(xs + j0 * 66);
    const float2* x1p = (const float2*)(xs + j1 * 66);
#pragma unroll 8
    for (int cc = 0; cc < 32; cc++) {
        float2 wv0 = w0p[cc], wv1 = w1p[cc];
        float2 xv0 = x0p[cc], xv1 = x1p[cc];
        u00 = fmaf(wv0.x, xv0.x, u00); u00 = fmaf(wv0.y, xv0.y, u00);
        u01 = fmaf(wv1.x, xv0.x, u01); u01 = fmaf(wv1.y, xv0.y, u01);
        u10 = fmaf(wv0.x, xv1.x, u10); u10 = fmaf(wv0.y, xv1.y, u10);
        u11 = fmaf(wv1.x, xv1.x, u11); u11 = fmaf(wv1.y, xv1.y, u11);
    }
    u00 -= mv0; u01 -= mv1; u10 -= mv0; u11 -= mv1;
    float ss0 = u00 * u00 + u01 * u01;
    float ss1 = u10 * u10 + u11 * u11;
#pragma unroll
    for (int o = 16; o; o >>= 1) {
        ss0 += __shfl_xor_sync(0xFFFFFFFFu, ss0, o);
        ss1 += __shfl_xor_sync(0xFFFFFFFFu, ss1, o);
    }
    float r0 = rsqrtf(ss0 + 1e-24f), r1 = rsqrtf(ss1 + 1e-24f);
    __nv_bfloat16* q0p = g_Qb + (size_t)(w * 4096 + nbase + j0) * 64;
    __nv_bfloat16* q1p = g_Qb + (size_t)(w * 4096 + nbase + j1) * 64;
    q0p[lane] = __float2bfloat16(u00 * r0);
    q0p[lane + 32] = __float2bfloat16(u01 * r0);
    q1p[lane] = __float2bfloat16(u10 * r1);
    q1p[lane + 32] = __float2bfloat16(u11 * r1);
}

// ---------- mma helpers ----------
__device__ __forceinline__ void ldsm4(unsigned addr, unsigned& r0, unsigned& r1,
                                      unsigned& r2, unsigned& r3) {
    asm volatile("ldmatrix.sync.aligned.m8n8.x4.shared.b16 {%0,%1,%2,%3}, [%4];"
                 : "=r"(r0), "=r"(r1), "=r"(r2), "=r"(r3) : "r"(addr));
}
__device__ __forceinline__ void ldsm4t(unsigned addr, unsigned& r0, unsigned& r1,
                                       unsigned& r2, unsigned& r3) {
    asm volatile("ldmatrix.sync.aligned.m8n8.x4.trans.shared.b16 {%0,%1,%2,%3}, [%4];"
                 : "=r"(r0), "=r"(r1), "=r"(r2), "=r"(r3) : "r"(addr));
}
__device__ __forceinline__ void mma16816(float* c, const unsigned* a, unsigned b0, unsigned b1) {
    asm volatile("mma.sync.aligned.m16n8k16.row.col.f32.bf16.bf16.f32 "
                 "{%0,%1,%2,%3},{%4,%5,%6,%7},{%8,%9},{%0,%1,%2,%3};"
                 : "+f"(c[0]), "+f"(c[1]), "+f"(c[2]), "+f"(c[3])
                 : "r"(a[0]), "r"(a[1]), "r"(a[2]), "r"(a[3]), "r"(b0), "r"(b1));
}
__device__ __forceinline__ void mma_tf32(float* c, unsigned a0, unsigned a1, unsigned a2,
                                         unsigned a3, unsigned b0, unsigned b1) {
    asm volatile("mma.sync.aligned.m16n8k8.row.col.f32.tf32.tf32.f32 "
                 "{%0,%1,%2,%3},{%4,%5,%6,%7},{%8,%9},{%0,%1,%2,%3};"
                 : "+f"(c[0]), "+f"(c[1]), "+f"(c[2]), "+f"(c[3])
                 : "r"(a0), "r"(a1), "r"(a2), "r"(a3), "r"(b0), "r"(b1));
}
__device__ __forceinline__ unsigned packbf(float lo, float hi) {
    __nv_bfloat162 h = __floats2bfloat162_rn(lo, hi);
    return *(unsigned*)&h;
}
__device__ __forceinline__ void cp16(unsigned dst, const void* src) {
    asm volatile("cp.async.cg.shared.global [%0], [%1], 16;" :: "r"(dst), "l"(src));
}

// ---------- attention: bf16 HMMA, 64q CTA x 4 warps, ILP2, double-buffered ----------
#define PITCHB 144       // bytes per smem row (72 bf16)
#define BUFB   36864     // one buffer: K(18432) + V(18432)
__global__ void __launch_bounds__(128, 2) attn_mma() {
    extern __shared__ char smx[];
    unsigned smU = (unsigned)__cvta_generic_to_shared(smx);
    int w = blockIdx.y;
    int qb = blockIdx.x * 64;
    int t = threadIdx.x, warp = t >> 5, lane = t & 31;
    int g = lane >> 2, tig = lane & 3;
    const __nv_bfloat16* Qg = g_Qb + (size_t)w * 4096 * 64;
    const __nv_bfloat16* Vg = g_Vb + (size_t)w * 4096 * 64;

    int q0 = qb + warp * 16;
    unsigned qa[4][4];
#pragma unroll
    for (int s = 0; s < 4; s++) {
        const __nv_bfloat16* bp = Qg + (q0 + g) * 64 + s * 16 + 2 * tig;
        qa[s][0] = *(const unsigned*)(bp);
        qa[s][1] = *(const unsigned*)(bp + 8 * 64);
        qa[s][2] = *(const unsigned*)(bp + 8);
        qa[s][3] = *(const unsigned*)(bp + 8 * 64 + 8);
    }

    float o[8][4];
#pragma unroll
    for (int i = 0; i < 8; i++)
#pragma unroll
        for (int jx = 0; jx < 4; jx++) o[i][jx] = 0.f;
    u64t rsA = 0ull, rsB = 0ull;

    int mi = lane >> 3, li = lane & 7;
    unsigned kOff = ((mi >> 1) * 8 + li) * PITCHB + (mi & 1) * 16;
    unsigned vOff = ((mi & 1) * 8 + li) * PITCHB + (mi >> 1) * 16;

    const u64t C18 = pk2(0.125f, 0.125f);
    const u64t K3 = pk2(0.1889038f, 0.1889038f);
    const u64t K2 = pk2(0.4964532f, 0.4964532f);
    const u64t K1 = pk2(1.0001804f, 1.0001804f);
    const u64t K0 = pk2(0.9999986f, 0.9999986f);

#define ISSUE(ch) do {                                                        \
        int _b = (ch) & 1;                                                    \
        unsigned _kd = smU + _b * BUFB, _vd = _kd + 18432;                    \
        const char* _ks = (const char*)(Qg + (ch) * 128 * 64);                \
        const char* _vs = (const char*)(Vg + (ch) * 128 * 64);                \
        _Pragma("unroll")                                                     \
        for (int _i = 0; _i < 8; _i++) {                                      \
            int _idx = t + _i * 128;                                          \
            int _r = _idx >> 3, _cg = _idx & 7;                               \
            unsigned _o = _r * PITCHB + _cg * 16;                             \
            unsigned _go = _r * 128 + _cg * 16;                               \
            cp16(_kd + _o, _ks + _go);                                        \
            cp16(_vd + _o, _vs + _go);                                        \
        }                                                                     \
        asm volatile("cp.async.commit_group;");                               \
    } while (0)

#define SOFTEXP(p0, p1, ea) do {                                              \
        u64t d0 = pk2(p0[0], p0[1]), d1 = pk2(p0[2], p0[3]);                  \
        u64t d2 = pk2(p1[0], p1[1]), d3 = pk2(p1[2], p1[3]);                  \
        u64t s0 = fma2(d0, C18, C18), s1 = fma2(d1, C18, C18);                \
        u64t s2 = fma2(d2, C18, C18), s3 = fma2(d3, C18, C18);                \
        u64t e0 = fma2(s0, K3, K2); e0 = fma2(s0, e0, K1); e0 = fma2(s0, e0, K0); \
        u64t e1 = fma2(s1, K3, K2); e1 = fma2(s1, e1, K1); e1 = fma2(s1, e1, K0); \
        u64t e2 = fma2(s2, K3, K2); e2 = fma2(s2, e2, K1); e2 = fma2(s2, e2, K0); \
        u64t e3 = fma2(s3, K3, K2); e3 = fma2(s3, e3, K1); e3 = fma2(s3, e3, K0); \
        rsA = add2(rsA, e0); rsB = add2(rsB, e1);                             \
        rsA = add2(rsA, e2); rsB = add2(rsB, e3);                             \
        float f0, f1;                                                         \
        upk2(e0, f0, f1); ea[0] = packbf(f0, f1);                             \
        upk2(e1, f0, f1); ea[1] = packbf(f0, f1);                             \
        upk2(e2, f0, f1); ea[2] = packbf(f0, f1);                             \
        upk2(e3, f0, f1); ea[3] = packbf(f0, f1);                             \
    } while (0)

    ISSUE(0);
    ISSUE(1);

    for (int ch = 0; ch < 32; ch++) {
        if (ch < 31) asm volatile("cp.async.wait_group 1;");
        else         asm volatile("cp.async.wait_group 0;");
        __syncthreads();
        unsigned ksU = smU + (ch & 1) * BUFB;
        unsigned vsU = ksU + 18432;

#pragma unroll
        for (int jp = 0; jp < 8; jp += 2) {
            float pA0[4] = {0.f, 0.f, 0.f, 0.f}, pA1[4] = {0.f, 0.f, 0.f, 0.f};
            float pB0[4] = {0.f, 0.f, 0.f, 0.f}, pB1[4] = {0.f, 0.f, 0.f, 0.f};
#pragma unroll
            for (int s = 0; s < 4; s++) {
                unsigned r0, r1, r2, r3;
                ldsm4(ksU + jp * (16 * PITCHB) + s * 32 + kOff, r0, r1, r2, r3);
                mma16816(pA0, qa[s], r0, r1);
                mma16816(pA1, qa[s], r2, r3);
                ldsm4(ksU + (jp + 1) * (16 * PITCHB) + s * 32 + kOff, r0, r1, r2, r3);
                mma16816(pB0, qa[s], r0, r1);
                mma16816(pB1, qa[s], r2, r3);
            }
            unsigned eaA[4], eaB[4];
            SOFTEXP(pA0, pA1, eaA);
            SOFTEXP(pB0, pB1, eaB);
#pragma unroll
            for (int cp = 0; cp < 4; cp++) {
                unsigned r0, r1, r2, r3;
                ldsm4t(vsU + jp * (16 * PITCHB) + cp * 32 + vOff, r0, r1, r2, r3);
                mma16816(o[2 * cp],     eaA, r0, r1);
                mma16816(o[2 * cp + 1], eaA, r2, r3);
                ldsm4t(vsU + (jp + 1) * (16 * PITCHB) + cp * 32 + vOff, r0, r1, r2, r3);
                mma16816(o[2 * cp],     eaB, r0, r1);
                mma16816(o[2 * cp + 1], eaB, r2, r3);
            }
        }
        __syncthreads();
        if (ch + 2 < 32) ISSUE(ch + 2);
    }

    float rs0a, rs0b, rs1a, rs1b;
    upk2(rsA, rs0a, rs0b); upk2(rsB, rs1a, rs1b);
    float rs0 = rs0a + rs0b, rs1 = rs1a + rs1b;
    rs0 += __shfl_xor_sync(0xFFFFFFFFu, rs0, 1);
    rs0 += __shfl_xor_sync(0xFFFFFFFFu, rs0, 2);
    rs1 += __shfl_xor_sync(0xFFFFFFFFu, rs1, 1);
    rs1 += __shfl_xor_sync(0xFFFFFFFFu, rs1, 2);
    float i0 = 1.f / rs0, i1 = 1.f / rs1;

    float* outp = g_attn + (size_t)(w * 4096 + q0) * 64;
#pragma unroll
    for (int c = 0; c < 8; c++) {
        int col = c * 8 + 2 * tig;
        *(float2*)(outp + g * 64 + col)       = make_float2(o[c][0] * i0, o[c][1] * i0);
        *(float2*)(outp + (g + 8) * 64 + col) = make_float2(o[c][2] * i1, o[c][3] * i1);
    }
}

// ---------- fused 1x1 conv (attn 64ch + unet 1ch) + bias + residual -> g_t ----------
__global__ void convl_fused(const float* __restrict__ unet, const float* __restrict__ x,
                            const float* __restrict__ bias) {
    __shared__ float w_s[4160];
    int t = threadIdx.x;
    for (int i = t; i < 4160; i += 256) w_s[i] = g_wlT[i];
    __syncthreads();
    int p = blockIdx.x * 128 + (t & 127);
    int cog = t >> 7;
    float acc[32];
#pragma unroll
    for (int i = 0; i < 32; i++) acc[i] = 0.f;
    for (int ci = 0; ci < 65; ci++) {
        float v = (ci < 64) ? g_attn[ci * 16384 + p] : unet[p];
        const float4* wr = (const float4*)(w_s + ci * 64 + cog * 32);
#pragma unroll
        for (int k = 0; k < 8; k++) {
            float4 wv = wr[k];
            acc[4 * k + 0] = fmaf(wv.x, v, acc[4 * k + 0]);
            acc[4 * k + 1] = fmaf(wv.y, v, acc[4 * k + 1]);
            acc[4 * k + 2] = fmaf(wv.z, v, acc[4 * k + 2]);
            acc[4 * k + 3] = fmaf(wv.w, v, acc[4 * k + 3]);
        }
    }
#pragma unroll
    for (int i = 0; i < 32; i++) {
        int co = cog * 32 + i;
        g_t[co * 16384 + p] = x[co * 16384 + p] + acc[i] + bias[co];
    }
}

// ---------- 3x3 conv (dilation D) + relu via tf32 HMMA implicit GEMM ----------
template <int D>
__global__ void __launch_bounds__(256) conv_tf32(const float* __restrict__ in,
                                                 const float* __restrict__ wB,
                                                 const float* __restrict__ bias,
                                                 float* __restrict__ out) {
    constexpr int IH = 8 + 2 * D, IW = 16 + 2 * D, INW = 8 * IH * IW;
    extern __shared__ float sm[];
    float* As  = sm;           // [128 px][73] tf32 (72 k used)
    float* Bs  = sm + 9344;    // [64 co][73]
    float* in_s = sm + 14016;  // [8 ci][IH][IW] fp32
    int t = threadIdx.x, warp = t >> 5, lane = t & 31;
    int g = lane >> 2, tig = lane & 3;
    int r0 = blockIdx.y * 8, c0 = blockIdx.x * 16;

    float o[8][4];
#pragma unroll
    for (int nb = 0; nb < 8; nb++) {
        float b0 = bias[nb * 8 + 2 * tig], b1 = bias[nb * 8 + 2 * tig + 1];
        o[nb][0] = b0; o[nb][1] = b1; o[nb][2] = b0; o[nb][3] = b1;
    }

    int px_b = t >> 1, y_b = px_b >> 4, x_b = px_b & 15;
    int ci0 = (t & 1) * 4;

    for (int grp = 0; grp < 8; grp++) {
        __syncthreads();
        for (int idx = t; idx < INW; idx += 256) {
            int ci = idx / (IH * IW), rem = idx - ci * (IH * IW);
            int rr = rem / IW, cc = rem - rr * IW;
            int gr = r0 - D + rr, gc = c0 - D + cc;
            float v = 0.f;
            if (gr >= 0 && gr < 128 && gc >= 0 && gc < 128)
                v = in[(grp * 8 + ci) * 16384 + gr * 128 + gc];
            in_s[idx] = v;
        }
#pragma unroll
        for (int pass = 0; pass < 18; pass++) {
            int idx = pass * 256 + t;
            int co = idx / 72, k = idx - co * 72;
            Bs[co * 73 + k] = wB[co * 576 + grp * 72 + k];
        }
        __syncthreads();
        // build im2col A tile (tf32): 4 ci x 9 taps per thread
        {
            const float* ip = in_s + ci0 * (IH * IW) + y_b * IW + x_b;
            float* ap = As + px_b * 73 + ci0 * 9;
#pragma unroll
            for (int cq = 0; cq < 4; cq++)
#pragma unroll
                for (int kh = 0; kh < 3; kh++)
#pragma unroll
                    for (int kw = 0; kw < 3; kw++)
                        ap[cq * 9 + kh * 3 + kw] = __uint_as_float(
                            cvt_tf32(ip[cq * IH * IW + (kh * D) * IW + kw * D]));
        }
        __syncthreads();
        const float* Ar = As + warp * 16 * 73;
#pragma unroll
        for (int kc = 0; kc < 9; kc++) {
            unsigned a0 = __float_as_uint(Ar[g * 73 + kc * 8 + tig]);
            unsigned a1 = __float_as_uint(Ar[(g + 8) * 73 + kc * 8 + tig]);
            unsigned a2 = __float_as_uint(Ar[g * 73 + kc * 8 + tig + 4]);
            unsigned a3 = __float_as_uint(Ar[(g + 8) * 73 + kc * 8 + tig + 4]);
#pragma unroll
            for (int nb = 0; nb < 8; nb++) {
                unsigned b0 = __float_as_uint(Bs[(nb * 8 + g) * 73 + kc * 8 + tig]);
                unsigned b1 = __float_as_uint(Bs[(nb * 8 + g) * 73 + kc * 8 + tig + 4]);
                mma_tf32(o[nb], a0, a1, a2, a3, b0, b1);
            }
        }
    }

    int gp = (r0 + warp) * 128 + c0;
#pragma unroll
    for (int nb = 0; nb < 8; nb++) {
        int co = nb * 8 + 2 * tig;
        out[co * 16384 + gp + g]           = fmaxf(o[nb][0], 0.f);
        out[(co + 1) * 16384 + gp + g]     = fmaxf(o[nb][1], 0.f);
        out[co * 16384 + gp + g + 8]       = fmaxf(o[nb][2], 0.f);
        out[(co + 1) * 16384 + gp + g + 8] = fmaxf(o[nb][3], 0.f);
    }
}

// ---------- final 1x1 conv + bias + residual -> d_out ----------
__global__ void conv1x1_final(const float* __restrict__ x, const float* __restrict__ bias,
                              float* __restrict__ out) {
    __shared__ float w_s[4096];
    int t = threadIdx.x;
    for (int i = t; i < 4096; i += 256) w_s[i] = g_w3T[i];
    __syncthreads();
    int p = blockIdx.x * 128 + (t & 127);
    int cog = t >> 7;
    float acc[32];
#pragma unroll
    for (int i = 0; i < 32; i++) acc[i] = 0.f;
    for (int ci = 0; ci < 64; ci++) {
        float v = g_z2[ci * 16384 + p];
        const float4* wr = (const float4*)(w_s + ci * 64 + cog * 32);
#pragma unroll
        for (int k = 0; k < 8; k++) {
            float4 wv = wr[k];
            acc[4 * k + 0] = fmaf(wv.x, v, acc[4 * k + 0]);
            acc[4 * k + 1] = fmaf(wv.y, v, acc[4 * k + 1]);
            acc[4 * k + 2] = fmaf(wv.z, v, acc[4 * k + 2]);
            acc[4 * k + 3] = fmaf(wv.w, v, acc[4 * k + 3]);
        }
    }
#pragma unroll
    for (int i = 0; i < 32; i++) {
        int co = cog * 32 + i;
        out[co * 16384 + p] = x[co * 16384 + p] + acc[i] + bias[co];
    }
}

extern "C" void kernel_launch(void* const* d_in, const int* in_sizes, int n_in,
                              void* d_out, int out_size) {
    const float* x     = (const float*)d_in[0];
    const float* unet  = (const float*)d_in[1];
    const float* wqk   = (const float*)d_in[2];
    const float* c1w   = (const float*)d_in[3];
    const float* c1b   = (const float*)d_in[4];
    const float* c2w   = (const float*)d_in[5];
    const float* c2b   = (const float*)d_in[6];
    const float* c3w   = (const float*)d_in[7];
    const float* c3b   = (const float*)d_in[8];
    const float* clw   = (const float*)d_in[9];
    const float* clb   = (const float*)d_in[10];
    float* out = (float*)d_out;

    int smem1 = (14016 + 8 * 10 * 18) * 4;   // 61824 B
    int smem2 = (14016 + 8 * 12 * 20) * 4;   // 63744 B
    cudaFuncSetAttribute(attn_mma, cudaFuncAttributeMaxDynamicSharedMemorySize, 2 * BUFB);
    cudaFuncSetAttribute(conv_tf32<1>, cudaFuncAttributeMaxDynamicSharedMemorySize, smem1);
    cudaFuncSetAttribute(conv_tf32<2>, cudaFuncAttributeMaxDynamicSharedMemorySize, smem2);

    mean1<<<128, 256>>>(x);
    prep_w2<<<144, 256>>>(c1w, c2w, c3w, clw, wqk);
    qv_build<<<1024, 256>>>(x, wqk);
    attn_mma<<<dim3(64, 4), 128, 2 * BUFB>>>();
    convl_fused<<<128, 256>>>(unet, x, clb);
    float* z1;  cudaGetSymbolAddress((void**)&z1, g_z1);
    float* z2;  cudaGetSymbolAddress((void**)&z2, g_z2);
    float* tt;  cudaGetSymbolAddress((void**)&tt, g_t);
    float* wc1; cudaGetSymbolAddress((void**)&wc1, g_wc1);
    float* wc2; cudaGetSymbolAddress((void**)&wc2, g_wc2);
    conv_tf32<1><<<dim3(8, 16), 256, smem1>>>(tt, wc1, c1b, z1);
    conv_tf32<2><<<dim3(8, 16), 256, smem2>>>(z1, wc2, c2b, z2);
    conv1x1_final<<<128, 256>>>(x, c3b, out);
}

// round 14
// speedup vs baseline: 3.8308x; 1.0809x over previous
#include <cuda_runtime.h>
#include <cuda_bf16.h>

typedef unsigned long long u64t;

// ---------- scratch ----------
__device__ float g_part[128];
__device__ float g_mvec[64];
__device__ int   g_ctr;
__device__ __align__(16) __nv_bfloat16 g_Qb[4 * 4096 * 64]; // [w][n][d] normalized Q (=K)
__device__ __align__(16) __nv_bfloat16 g_Vb[4 * 4096 * 64]; // [w][n][c]
__device__ float g_attn[1048576];                           // raw reshape (64,128,128)
__device__ float g_t [1048576];
__device__ float g_z1[1048576];
__device__ float g_wc1[36864];   // tf32 weights, [co][ci*9+tap]
__device__ float g_wc2[36864];
__device__ float g_w3c[64 * 64]; // tf32, [co][ci]
__device__ float g_wlT[65 * 64];

// ---------- helpers ----------
__device__ __forceinline__ u64t pk2(float a, float b) {
    u64t r; asm("mov.b64 %0,{%1,%2};" : "=l"(r) : "f"(a), "f"(b)); return r;
}
__device__ __forceinline__ void upk2(u64t v, float& a, float& b) {
    asm("mov.b64 {%0,%1},%2;" : "=f"(a), "=f"(b) : "l"(v));
}
__device__ __forceinline__ u64t fma2(u64t a, u64t b, u64t c) {
    u64t d; asm("fma.rn.f32x2 %0,%1,%2,%3;" : "=l"(d) : "l"(a), "l"(b), "l"(c)); return d;
}
__device__ __forceinline__ u64t add2(u64t a, u64t b) {
    u64t d; asm("add.rn.f32x2 %0,%1,%2;" : "=l"(d) : "l"(a), "l"(b)); return d;
}
__device__ __forceinline__ unsigned cvt_tf32(float f) {
    unsigned u; asm("cvt.rna.tf32.f32 %0,%1;" : "=r"(u) : "f"(f)); return u;
}
__device__ __forceinline__ unsigned packbf(float lo, float hi) {
    __nv_bfloat162 h = __floats2bfloat162_rn(lo, hi);
    return *(unsigned*)&h;
}
__device__ __forceinline__ void cp16(unsigned dst, const void* src) {
    asm volatile("cp.async.cg.shared.global [%0], [%1], 16;" :: "r"(dst), "l"(src));
}

// ---------- merged: mean stage1 + weight prep + mean stage2 ----------
__global__ void prep_all(const float* __restrict__ x,  const float* __restrict__ w1,
                         const float* __restrict__ w2, const float* __restrict__ w3,
                         const float* __restrict__ wl, const float* __restrict__ wqk) {
    int t = threadIdx.x, bid = blockIdx.x;       // 144 blocks x 256
    if (bid < 128) {
        __shared__ float red[256];
        int base = bid * 8192;
        float s = 0.f;
#pragma unroll
        for (int k = 0; k < 32; k++) s += x[base + k * 256 + t];
        red[t] = s; __syncthreads();
        for (int o = 128; o; o >>= 1) { if (t < o) red[t] += red[t + o]; __syncthreads(); }
        if (t == 0) g_part[bid] = red[0];
    }
    int i = bid * 256 + t;
    g_wc1[i] = __uint_as_float(cvt_tf32(w1[i]));
    g_wc2[i] = __uint_as_float(cvt_tf32(w2[i]));
    if (i < 4096) g_w3c[i] = __uint_as_float(cvt_tf32(w3[i]));
    if (i < 4160) { int co = i / 65, ci = i - co * 65; g_wlT[ci * 64 + co] = wl[i]; }
    __syncthreads();
    __shared__ int lastf;
    if (t == 0) {
        __threadfence();
        lastf = (atomicAdd(&g_ctr, 1) == 143);
    }
    __syncthreads();
    if (lastf) {
        __threadfence();
        __shared__ float red2[128];
        __shared__ float m_sh;
        if (t < 128) red2[t] = g_part[t];
        __syncthreads();
        for (int o = 64; o; o >>= 1) { if (t < 128 && t < o) red2[t] += red2[t + o]; __syncthreads(); }
        if (t == 0) { m_sh = red2[0] * (1.0f / 1048576.0f); g_ctr = 0; }
        __syncthreads();
        if (t < 64) {
            float cs = 0.f;
            for (int c = 0; c < 64; c++) cs += wqk[c * 64 + t];
            g_mvec[t] = m_sh * cs;
        }
    }
}

// ---------- build normalized Q (bf16) and V (bf16); 16 rows/block ----------
__global__ void __launch_bounds__(256) qv_build(const float* __restrict__ x,
                                                const float* __restrict__ wqk) {
    __shared__ float wT[64 * 66];   // [e][c] pitch 66
    __shared__ float xs[16 * 66];   // [j][c] pitch 66
    int b = blockIdx.x;             // 1024 blocks
    int w = b >> 8, rb = b & 255;
    int hs = rb >> 2, ws0 = (rb & 3) * 16;
    int dh = w >> 1, dw = w & 1;
    int t = threadIdx.x;
    int h = 2 * hs + dh;
    for (int i = t; i < 4096; i += 256)
        wT[(i & 63) * 66 + (i >> 6)] = wqk[i];
#pragma unroll
    for (int pass = 0; pass < 4; pass++) {
        int i = pass * 256 + t;
        int j = i & 15, c = i >> 4;
        xs[j * 66 + c] = x[c * 16384 + h * 128 + 2 * (ws0 + j) + dw];
    }
    __syncthreads();
    int nbase = hs * 64 + ws0;
#pragma unroll
    for (int pass = 0; pass < 4; pass++) {       // V bf16
        int i = pass * 256 + t;
        int c = i & 63, j = i >> 6;
        g_Vb[(size_t)(w * 4096 + nbase + j) * 64 + c] = __float2bfloat16(xs[j * 66 + c]);
    }
    int lane = t & 31, warp = t >> 5;
    int j0 = warp * 2, j1 = j0 + 1;
    float mv0 = g_mvec[lane], mv1 = g_mvec[lane + 32];
    float u00 = 0.f, u01 = 0.f, u10 = 0.f, u11 = 0.f;
    const float2* w0p = (const float2*)(wT + lane * 66);
    const float2* w1p = (const float2*)(wT + (lane + 32) * 66);
    const float2* x0p = (const float2*)(xs + j0 * 66);
    const float2* x1p = (const float2*)(xs + j1 * 66);
#pragma unroll 8
    for (int cc = 0; cc < 32; cc++) {
        float2 wv0 = w0p[cc], wv1 = w1p[cc];
        float2 xv0 = x0p[cc], xv1 = x1p[cc];
        u00 = fmaf(wv0.x, xv0.x, u00); u00 = fmaf(wv0.y, xv0.y, u00);
        u01 = fmaf(wv1.x, xv0.x, u01); u01 = fmaf(wv1.y, xv0.y, u01);
        u10 = fmaf(wv0.x, xv1.x, u10); u10 = fmaf(wv0.y, xv1.y, u10);
        u11 = fmaf(wv1.x, xv1.x, u11); u11 = fmaf(wv1.y, xv1.y, u11);
    }
    u00 -= mv0; u01 -= mv1; u10 -= mv0; u11 -= mv1;
    float ss0 = u00 * u00 + u01 * u01;
    float ss1 = u10 * u10 + u11 * u11;
#pragma unroll
    for (int o = 16; o; o >>= 1) {
        ss0 += __shfl_xor_sync(0xFFFFFFFFu, ss0, o);
        ss1 += __shfl_xor_sync(0xFFFFFFFFu, ss1, o);
    }
    float r0 = rsqrtf(ss0 + 1e-24f), r1 = rsqrtf(ss1 + 1e-24f);
    __nv_bfloat16* q0p = g_Qb + (size_t)(w * 4096 + nbase + j0) * 64;
    __nv_bfloat16* q1p = g_Qb + (size_t)(w * 4096 + nbase + j1) * 64;
    q0p[lane] = __float2bfloat16(u00 * r0);
    q0p[lane + 32] = __float2bfloat16(u01 * r0);
    q1p[lane] = __float2bfloat16(u10 * r1);
    q1p[lane + 32] = __float2bfloat16(u11 * r1);
}

// ---------- mma helpers ----------
__device__ __forceinline__ void ldsm4(unsigned addr, unsigned& r0, unsigned& r1,
                                      unsigned& r2, unsigned& r3) {
    asm volatile("ldmatrix.sync.aligned.m8n8.x4.shared.b16 {%0,%1,%2,%3}, [%4];"
                 : "=r"(r0), "=r"(r1), "=r"(r2), "=r"(r3) : "r"(addr));
}
__device__ __forceinline__ void ldsm4t(unsigned addr, unsigned& r0, unsigned& r1,
                                       unsigned& r2, unsigned& r3) {
    asm volatile("ldmatrix.sync.aligned.m8n8.x4.trans.shared.b16 {%0,%1,%2,%3}, [%4];"
                 : "=r"(r0), "=r"(r1), "=r"(r2), "=r"(r3) : "r"(addr));
}
__device__ __forceinline__ void mma16816(float* c, const unsigned* a, unsigned b0, unsigned b1) {
    asm volatile("mma.sync.aligned.m16n8k16.row.col.f32.bf16.bf16.f32 "
                 "{%0,%1,%2,%3},{%4,%5,%6,%7},{%8,%9},{%0,%1,%2,%3};"
                 : "+f"(c[0]), "+f"(c[1]), "+f"(c[2]), "+f"(c[3])
                 : "r"(a[0]), "r"(a[1]), "r"(a[2]), "r"(a[3]), "r"(b0), "r"(b1));
}
__device__ __forceinline__ void mma_tf32(float* c, unsigned a0, unsigned a1, unsigned a2,
                                         unsigned a3, unsigned b0, unsigned b1) {
    asm volatile("mma.sync.aligned.m16n8k8.row.col.f32.tf32.tf32.f32 "
                 "{%0,%1,%2,%3},{%4,%5,%6,%7},{%8,%9},{%0,%1,%2,%3};"
                 : "+f"(c[0]), "+f"(c[1]), "+f"(c[2]), "+f"(c[3])
                 : "r"(a0), "r"(a1), "r"(a2), "r"(a3), "r"(b0), "r"(b1));
}

// ---------- attention: bf16 HMMA, 64q CTA x 4 warps, ILP2, double-buffered ----------
#define PITCHB 144       // bytes per smem row (72 bf16)
#define BUFB   36864     // one buffer: K(18432) + V(18432)
__global__ void __launch_bounds__(128, 2) attn_mma() {
    extern __shared__ char smx[];
    unsigned smU = (unsigned)__cvta_generic_to_shared(smx);
    int w = blockIdx.y;
    int qb = blockIdx.x * 64;
    int t = threadIdx.x, warp = t >> 5, lane = t & 31;
    int g = lane >> 2, tig = lane & 3;
    const __nv_bfloat16* Qg = g_Qb + (size_t)w * 4096 * 64;
    const __nv_bfloat16* Vg = g_Vb + (size_t)w * 4096 * 64;

    int q0 = qb + warp * 16;
    unsigned qa[4][4];
#pragma unroll
    for (int s = 0; s < 4; s++) {
        const __nv_bfloat16* bp = Qg + (q0 + g) * 64 + s * 16 + 2 * tig;
        qa[s][0] = *(const unsigned*)(bp);
        qa[s][1] = *(const unsigned*)(bp + 8 * 64);
        qa[s][2] = *(const unsigned*)(bp + 8);
        qa[s][3] = *(const unsigned*)(bp + 8 * 64 + 8);
    }

    float o[8][4];
#pragma unroll
    for (int i = 0; i < 8; i++)
#pragma unroll
        for (int jx = 0; jx < 4; jx++) o[i][jx] = 0.f;
    u64t rsA = 0ull, rsB = 0ull;

    int mi = lane >> 3, li = lane & 7;
    unsigned kOff = ((mi >> 1) * 8 + li) * PITCHB + (mi & 1) * 16;
    unsigned vOff = ((mi & 1) * 8 + li) * PITCHB + (mi >> 1) * 16;

    const u64t C18 = pk2(0.125f, 0.125f);
    const u64t K3 = pk2(0.1889038f, 0.1889038f);
    const u64t K2 = pk2(0.4964532f, 0.4964532f);
    const u64t K1 = pk2(1.0001804f, 1.0001804f);
    const u64t K0 = pk2(0.9999986f, 0.9999986f);

#define ISSUE(ch) do {                                                        \
        int _b = (ch) & 1;                                                    \
        unsigned _kd = smU + _b * BUFB, _vd = _kd + 18432;                    \
        const char* _ks = (const char*)(Qg + (ch) * 128 * 64);                \
        const char* _vs = (const char*)(Vg + (ch) * 128 * 64);                \
        _Pragma("unroll")                                                     \
        for (int _i = 0; _i < 8; _i++) {                                      \
            int _idx = t + _i * 128;                                          \
            int _r = _idx >> 3, _cg = _idx & 7;                               \
            unsigned _o = _r * PITCHB + _cg * 16;                             \
            unsigned _go = _r * 128 + _cg * 16;                               \
            cp16(_kd + _o, _ks + _go);                                        \
            cp16(_vd + _o, _vs + _go);                                        \
        }                                                                     \
        asm volatile("cp.async.commit_group;");                               \
    } while (0)

#define SOFTEXP(p0, p1, ea) do {                                              \
        u64t d0 = pk2(p0[0], p0[1]), d1 = pk2(p0[2], p0[3]);                  \
        u64t d2 = pk2(p1[0], p1[1]), d3 = pk2(p1[2], p1[3]);                  \
        u64t s0 = fma2(d0, C18, C18), s1 = fma2(d1, C18, C18);                \
        u64t s2 = fma2(d2, C18, C18), s3 = fma2(d3, C18, C18);                \
        u64t e0 = fma2(s0, K3, K2); e0 = fma2(s0, e0, K1); e0 = fma2(s0, e0, K0); \
        u64t e1 = fma2(s1, K3, K2); e1 = fma2(s1, e1, K1); e1 = fma2(s1, e1, K0); \
        u64t e2 = fma2(s2, K3, K2); e2 = fma2(s2, e2, K1); e2 = fma2(s2, e2, K0); \
        u64t e3 = fma2(s3, K3, K2); e3 = fma2(s3, e3, K1); e3 = fma2(s3, e3, K0); \
        rsA = add2(rsA, e0); rsB = add2(rsB, e1);                             \
        rsA = add2(rsA, e2); rsB = add2(rsB, e3);                             \
        float f0, f1;                                                         \
        upk2(e0, f0, f1); ea[0] = packbf(f0, f1);                             \
        upk2(e1, f0, f1); ea[1] = packbf(f0, f1);                             \
        upk2(e2, f0, f1); ea[2] = packbf(f0, f1);                             \
        upk2(e3, f0, f1); ea[3] = packbf(f0, f1);                             \
    } while (0)

    ISSUE(0);
    ISSUE(1);

    for (int ch = 0; ch < 32; ch++) {
        if (ch < 31) asm volatile("cp.async.wait_group 1;");
        else         asm volatile("cp.async.wait_group 0;");
        __syncthreads();
        unsigned ksU = smU + (ch & 1) * BUFB;
        unsigned vsU = ksU + 18432;

#pragma unroll
        for (int jp = 0; jp < 8; jp += 2) {
            float pA0[4] = {0.f, 0.f, 0.f, 0.f}, pA1[4] = {0.f, 0.f, 0.f, 0.f};
            float pB0[4] = {0.f, 0.f, 0.f, 0.f}, pB1[4] = {0.f, 0.f, 0.f, 0.f};
#pragma unroll
            for (int s = 0; s < 4; s++) {
                unsigned r0, r1, r2, r3;
                ldsm4(ksU + jp * (16 * PITCHB) + s * 32 + kOff, r0, r1, r2, r3);
                mma16816(pA0, qa[s], r0, r1);
                mma16816(pA1, qa[s], r2, r3);
                ldsm4(ksU + (jp + 1) * (16 * PITCHB) + s * 32 + kOff, r0, r1, r2, r3);
                mma16816(pB0, qa[s], r0, r1);
                mma16816(pB1, qa[s], r2, r3);
            }
            unsigned eaA[4], eaB[4];
            SOFTEXP(pA0, pA1, eaA);
            SOFTEXP(pB0, pB1, eaB);
#pragma unroll
            for (int cp = 0; cp < 4; cp++) {
                unsigned r0, r1, r2, r3;
                ldsm4t(vsU + jp * (16 * PITCHB) + cp * 32 + vOff, r0, r1, r2, r3);
                mma16816(o[2 * cp],     eaA, r0, r1);
                mma16816(o[2 * cp + 1], eaA, r2, r3);
                ldsm4t(vsU + (jp + 1) * (16 * PITCHB) + cp * 32 + vOff, r0, r1, r2, r3);
                mma16816(o[2 * cp],     eaB, r0, r1);
                mma16816(o[2 * cp + 1], eaB, r2, r3);
            }
        }
        __syncthreads();
        if (ch + 2 < 32) ISSUE(ch + 2);
    }

    float rs0a, rs0b, rs1a, rs1b;
    upk2(rsA, rs0a, rs0b); upk2(rsB, rs1a, rs1b);
    float rs0 = rs0a + rs0b, rs1 = rs1a + rs1b;
    rs0 += __shfl_xor_sync(0xFFFFFFFFu, rs0, 1);
    rs0 += __shfl_xor_sync(0xFFFFFFFFu, rs0, 2);
    rs1 += __shfl_xor_sync(0xFFFFFFFFu, rs1, 1);
    rs1 += __shfl_xor_sync(0xFFFFFFFFu, rs1, 2);
    float i0 = 1.f / rs0, i1 = 1.f / rs1;

    float* outp = g_attn + (size_t)(w * 4096 + q0) * 64;
#pragma unroll
    for (int c = 0; c < 8; c++) {
        int col = c * 8 + 2 * tig;
        *(float2*)(outp + g * 64 + col)       = make_float2(o[c][0] * i0, o[c][1] * i0);
        *(float2*)(outp + (g + 8) * 64 + col) = make_float2(o[c][2] * i1, o[c][3] * i1);
    }
}

// ---------- fused 1x1 conv (attn 64ch + unet 1ch) + bias + residual -> g_t ----------
__global__ void convl_fused(const float* __restrict__ unet, const float* __restrict__ x,
                            const float* __restrict__ bias) {
    __shared__ float w_s[4160];
    int t = threadIdx.x;
    for (int i = t; i < 4160; i += 256) w_s[i] = g_wlT[i];
    __syncthreads();
    int p = blockIdx.x * 128 + (t & 127);
    int cog = t >> 7;
    float acc[32];
#pragma unroll
    for (int i = 0; i < 32; i++) acc[i] = 0.f;
    for (int ci = 0; ci < 65; ci++) {
        float v = (ci < 64) ? g_attn[ci * 16384 + p] : unet[p];
        const float4* wr = (const float4*)(w_s + ci * 64 + cog * 32);
#pragma unroll
        for (int k = 0; k < 8; k++) {
            float4 wv = wr[k];
            acc[4 * k + 0] = fmaf(wv.x, v, acc[4 * k + 0]);
            acc[4 * k + 1] = fmaf(wv.y, v, acc[4 * k + 1]);
            acc[4 * k + 2] = fmaf(wv.z, v, acc[4 * k + 2]);
            acc[4 * k + 3] = fmaf(wv.w, v, acc[4 * k + 3]);
        }
    }
#pragma unroll
    for (int i = 0; i < 32; i++) {
        int co = cog * 32 + i;
        g_t[co * 16384 + p] = x[co * 16384 + p] + acc[i] + bias[co];
    }
}

// ---------- 3x3 conv (dil D) via tf32 mma; FUSE: + 1x1 conv3 + bias + residual ----------
template <int D, bool FUSE>
__global__ void __launch_bounds__(256) conv_tf32(const float* __restrict__ in,
                                                 const float* __restrict__ wB,
                                                 const float* __restrict__ bias,
                                                 float* __restrict__ out,
                                                 const float* __restrict__ xres,
                                                 const float* __restrict__ b3) {
    constexpr int IH = 8 + 2 * D, IW = 16 + 2 * D, INW = 8 * IH * IW;
    extern __shared__ float sm[];
    float* As  = sm;           // [128 px][73]
    float* Bs  = sm + 9344;    // [64 co][73]
    float* in_s = sm + 14016;  // [8 ci][IH][IW]
    int t = threadIdx.x, warp = t >> 5, lane = t & 31;
    int g = lane >> 2, tig = lane & 3;
    int r0 = blockIdx.y * 8, c0 = blockIdx.x * 16;

    float o[8][4];
#pragma unroll
    for (int nb = 0; nb < 8; nb++) {
        float b0 = bias[nb * 8 + 2 * tig], b1 = bias[nb * 8 + 2 * tig + 1];
        o[nb][0] = b0; o[nb][1] = b1; o[nb][2] = b0; o[nb][3] = b1;
    }

    int px_b = t >> 1, y_b = px_b >> 4, x_b = px_b & 15;
    int ci0 = (t & 1) * 4;

    for (int grp = 0; grp < 8; grp++) {
        __syncthreads();
        for (int idx = t; idx < INW; idx += 256) {
            int ci = idx / (IH * IW), rem = idx - ci * (IH * IW);
            int rr = rem / IW, cc = rem - rr * IW;
            int gr = r0 - D + rr, gc = c0 - D + cc;
            float v = 0.f;
            if (gr >= 0 && gr < 128 && gc >= 0 && gc < 128)
                v = in[(grp * 8 + ci) * 16384 + gr * 128 + gc];
            in_s[idx] = v;
        }
#pragma unroll
        for (int pass = 0; pass < 18; pass++) {
            int idx = pass * 256 + t;
            int co = idx / 72, k = idx - co * 72;
            Bs[co * 73 + k] = wB[co * 576 + grp * 72 + k];
        }
        __syncthreads();
        {
            const float* ip = in_s + ci0 * (IH * IW) + y_b * IW + x_b;
            float* ap = As + px_b * 73 + ci0 * 9;
#pragma unroll
            for (int cq = 0; cq < 4; cq++)
#pragma unroll
                for (int kh = 0; kh < 3; kh++)
#pragma unroll
                    for (int kw = 0; kw < 3; kw++)
                        ap[cq * 9 + kh * 3 + kw] = __uint_as_float(
                            cvt_tf32(ip[cq * IH * IW + (kh * D) * IW + kw * D]));
        }
        __syncthreads();
        const float* Ar = As + warp * 16 * 73;
#pragma unroll
        for (int kc = 0; kc < 9; kc++) {
            unsigned a0 = __float_as_uint(Ar[g * 73 + kc * 8 + tig]);
            unsigned a1 = __float_as_uint(Ar[(g + 8) * 73 + kc * 8 + tig]);
            unsigned a2 = __float_as_uint(Ar[g * 73 + kc * 8 + tig + 4]);
            unsigned a3 = __float_as_uint(Ar[(g + 8) * 73 + kc * 8 + tig + 4]);
#pragma unroll
            for (int nb = 0; nb < 8; nb++) {
                unsigned b0 = __float_as_uint(Bs[(nb * 8 + g) * 73 + kc * 8 + tig]);
                unsigned b1 = __float_as_uint(Bs[(nb * 8 + g) * 73 + kc * 8 + tig + 4]);
                mma_tf32(o[nb], a0, a1, a2, a3, b0, b1);
            }
        }
    }

    if (!FUSE) {
        int gp = (r0 + warp) * 128 + c0;
#pragma unroll
        for (int nb = 0; nb < 8; nb++) {
            int co = nb * 8 + 2 * tig;
            out[co * 16384 + gp + g]           = fmaxf(o[nb][0], 0.f);
            out[(co + 1) * 16384 + gp + g]     = fmaxf(o[nb][1], 0.f);
            out[co * 16384 + gp + g + 8]       = fmaxf(o[nb][2], 0.f);
            out[(co + 1) * 16384 + gp + g + 8] = fmaxf(o[nb][3], 0.f);
        }
    } else {
        // z2 = relu(o) -> smem (As reused, [128 px][65]); then out = x + b3 + W3 @ z2
        __syncthreads();
#pragma unroll
        for (int nb = 0; nb < 8; nb++) {
            int co = nb * 8 + 2 * tig;
            As[(warp * 16 + g) * 65 + co]         = fmaxf(o[nb][0], 0.f);
            As[(warp * 16 + g) * 65 + co + 1]     = fmaxf(o[nb][1], 0.f);
            As[(warp * 16 + g + 8) * 65 + co]     = fmaxf(o[nb][2], 0.f);
            As[(warp * 16 + g + 8) * 65 + co + 1] = fmaxf(o[nb][3], 0.f);
        }
#pragma unroll
        for (int pass = 0; pass < 16; pass++) {    // W3 (already tf32) -> Bs pitch 65
            int idx = pass * 256 + t;
            Bs[(idx >> 6) * 65 + (idx & 63)] = g_w3c[idx];
        }
        __syncthreads();
        float o2[8][4];
#pragma unroll
        for (int nb = 0; nb < 8; nb++) {
            float b0 = b3[nb * 8 + 2 * tig], b1 = b3[nb * 8 + 2 * tig + 1];
            o2[nb][0] = b0; o2[nb][1] = b1; o2[nb][2] = b0; o2[nb][3] = b1;
        }
        const float* Ar2 = As + warp * 16 * 65;
#pragma unroll
        for (int kc = 0; kc < 8; kc++) {
            unsigned a0 = cvt_tf32(Ar2[g * 65 + kc * 8 + tig]);
            unsigned a1 = cvt_tf32(Ar2[(g + 8) * 65 + kc * 8 + tig]);
            unsigned a2 = cvt_tf32(Ar2[g * 65 + kc * 8 + tig + 4]);
            unsigned a3 = cvt_tf32(Ar2[(g + 8) * 65 + kc * 8 + tig + 4]);
#pragma unroll
            for (int nb = 0; nb < 8; nb++) {
                unsigned b0 = __float_as_uint(Bs[(nb * 8 + g) * 65 + kc * 8 + tig]);
                unsigned b1 = __float_as_uint(Bs[(nb * 8 + g) * 65 + kc * 8 + tig + 4]);
                mma_tf32(o2[nb], a0, a1, a2, a3, b0, b1);
            }
        }
        int gp = (r0 + warp) * 128 + c0;
#pragma unroll
        for (int nb = 0; nb < 8; nb++) {
            int co = nb * 8 + 2 * tig;
            out[co * 16384 + gp + g]           = xres[co * 16384 + gp + g]           + o2[nb][0];
            out[(co + 1) * 16384 + gp + g]     = xres[(co + 1) * 16384 + gp + g]     + o2[nb][1];
            out[co * 16384 + gp + g + 8]       = xres[co * 16384 + gp + g + 8]       + o2[nb][2];
            out[(co + 1) * 16384 + gp + g + 8] = xres[(co + 1) * 16384 + gp + g + 8] + o2[nb][3];
        }
    }
}

extern "C" void kernel_launch(void* const* d_in, const int* in_sizes, int n_in,
                              void* d_out, int out_size) {
    const float* x     = (const float*)d_in[0];
    const float* unet  = (const float*)d_in[1];
    const float* wqk   = (const float*)d_in[2];
    const float* c1w   = (const float*)d_in[3];
    const float* c1b   = (const float*)d_in[4];
    const float* c2w   = (const float*)d_in[5];
    const float* c2b   = (const float*)d_in[6];
    const float* c3w   = (const float*)d_in[7];
    const float* c3b   = (const float*)d_in[8];
    const float* clw   = (const float*)d_in[9];
    const float* clb   = (const float*)d_in[10];
    float* out = (float*)d_out;

    int smem1 = (14016 + 8 * 10 * 18) * 4;
    int smem2 = (14016 + 8 * 12 * 20) * 4;
    cudaFuncSetAttribute(attn_mma, cudaFuncAttributeMaxDynamicSharedMemorySize, 2 * BUFB);
    cudaFuncSetAttribute(conv_tf32<1, false>, cudaFuncAttributeMaxDynamicSharedMemorySize, smem1);
    cudaFuncSetAttribute(conv_tf32<2, true>,  cudaFuncAttributeMaxDynamicSharedMemorySize, smem2);

    prep_all<<<144, 256>>>(x, c1w, c2w, c3w, clw, wqk);
    qv_build<<<1024, 256>>>(x, wqk);
    attn_mma<<<dim3(64, 4), 128, 2 * BUFB>>>();
    convl_fused<<<128, 256>>>(unet, x, clb);
    float* z1;  cudaGetSymbolAddress((void**)&z1, g_z1);
    float* tt;  cudaGetSymbolAddress((void**)&tt, g_t);
    float* wc1; cudaGetSymbolAddress((void**)&wc1, g_wc1);
    float* wc2; cudaGetSymbolAddress((void**)&wc2, g_wc2);
    conv_tf32<1, false><<<dim3(8, 16), 256, smem1>>>(tt, wc1, c1b, z1, nullptr, nullptr);
    conv_tf32<2, true><<<dim3(8, 16), 256, smem2>>>(z1, wc2, c2b, out, x, c3b);
}

// round 15
// speedup vs baseline: 3.9672x; 1.0356x over previous
#include <cuda_runtime.h>
#include <cuda_bf16.h>

typedef unsigned long long u64t;

// ---------- scratch ----------
__device__ float g_part[128];
__device__ float g_mvec[64];
__device__ int   g_ctr;
__device__ __align__(16) __nv_bfloat16 g_Qb[4 * 4096 * 64]; // [w][n][d] normalized Q (=K)
__device__ __align__(16) __nv_bfloat16 g_Vb[4 * 4096 * 64]; // [w][n][c]
__device__ float g_attn[1048576];                           // raw reshape (64,128,128)
__device__ float g_t [1048576];
__device__ float g_z1[1048576];
__device__ float g_wc1[36864];   // tf32 weights, [co][ci*9+tap]
__device__ float g_wc2[36864];
__device__ float g_w3c[64 * 64]; // tf32, [co][ci]
__device__ float g_wlT[65 * 64];

// ---------- helpers ----------
__device__ __forceinline__ u64t pk2(float a, float b) {
    u64t r; asm("mov.b64 %0,{%1,%2};" : "=l"(r) : "f"(a), "f"(b)); return r;
}
__device__ __forceinline__ void upk2(u64t v, float& a, float& b) {
    asm("mov.b64 {%0,%1},%2;" : "=f"(a), "=f"(b) : "l"(v));
}
__device__ __forceinline__ u64t fma2(u64t a, u64t b, u64t c) {
    u64t d; asm("fma.rn.f32x2 %0,%1,%2,%3;" : "=l"(d) : "l"(a), "l"(b), "l"(c)); return d;
}
__device__ __forceinline__ u64t add2(u64t a, u64t b) {
    u64t d; asm("add.rn.f32x2 %0,%1,%2;" : "=l"(d) : "l"(a), "l"(b)); return d;
}
__device__ __forceinline__ unsigned cvt_tf32(float f) {
    unsigned u; asm("cvt.rna.tf32.f32 %0,%1;" : "=r"(u) : "f"(f)); return u;
}
__device__ __forceinline__ unsigned packbf(float lo, float hi) {
    __nv_bfloat162 h = __floats2bfloat162_rn(lo, hi);
    return *(unsigned*)&h;
}
__device__ __forceinline__ void cp16(unsigned dst, const void* src) {
    asm volatile("cp.async.cg.shared.global [%0], [%1], 16;" :: "r"(dst), "l"(src));
}

// ---------- merged: mean stage1 + weight prep + mean stage2 ----------
__global__ void prep_all(const float* __restrict__ x,  const float* __restrict__ w1,
                         const float* __restrict__ w2, const float* __restrict__ w3,
                         const float* __restrict__ wl, const float* __restrict__ wqk) {
    int t = threadIdx.x, bid = blockIdx.x;       // 144 blocks x 256
    if (bid < 128) {
        __shared__ float red[256];
        int base = bid * 8192;
        float s = 0.f;
#pragma unroll
        for (int k = 0; k < 32; k++) s += x[base + k * 256 + t];
        red[t] = s; __syncthreads();
        for (int o = 128; o; o >>= 1) { if (t < o) red[t] += red[t + o]; __syncthreads(); }
        if (t == 0) g_part[bid] = red[0];
    }
    int i = bid * 256 + t;
    g_wc1[i] = __uint_as_float(cvt_tf32(w1[i]));
    g_wc2[i] = __uint_as_float(cvt_tf32(w2[i]));
    if (i < 4096) g_w3c[i] = __uint_as_float(cvt_tf32(w3[i]));
    if (i < 4160) { int co = i / 65, ci = i - co * 65; g_wlT[ci * 64 + co] = wl[i]; }
    __syncthreads();
    __shared__ int lastf;
    if (t == 0) {
        __threadfence();
        lastf = (atomicAdd(&g_ctr, 1) == 143);
    }
    __syncthreads();
    if (lastf) {
        __threadfence();
        __shared__ float red2[128];
        __shared__ float m_sh;
        if (t < 128) red2[t] = g_part[t];
        __syncthreads();
        for (int o = 64; o; o >>= 1) { if (t < 128 && t < o) red2[t] += red2[t + o]; __syncthreads(); }
        if (t == 0) { m_sh = red2[0] * (1.0f / 1048576.0f); g_ctr = 0; }
        __syncthreads();
        if (t < 64) {
            float cs = 0.f;
            for (int c = 0; c < 64; c++) cs += wqk[c * 64 + t];
            g_mvec[t] = m_sh * cs;
        }
    }
}

// ---------- build normalized Q (bf16) and V (bf16); 16 rows/block ----------
__global__ void __launch_bounds__(256) qv_build(const float* __restrict__ x,
                                                const float* __restrict__ wqk) {
    __shared__ float wT[64 * 66];   // [e][c] pitch 66
    __shared__ float xs[16 * 66];   // [j][c] pitch 66
    int b = blockIdx.x;             // 1024 blocks
    int w = b >> 8, rb = b & 255;
    int hs = rb >> 2, ws0 = (rb & 3) * 16;
    int dh = w >> 1, dw = w & 1;
    int t = threadIdx.x;
    int h = 2 * hs + dh;
    for (int i = t; i < 4096; i += 256)
        wT[(i & 63) * 66 + (i >> 6)] = wqk[i];
#pragma unroll
    for (int pass = 0; pass < 4; pass++) {
        int i = pass * 256 + t;
        int j = i & 15, c = i >> 4;
        xs[j * 66 + c] = x[c * 16384 + h * 128 + 2 * (ws0 + j) + dw];
    }
    __syncthreads();
    int nbase = hs * 64 + ws0;
#pragma unroll
    for (int pass = 0; pass < 4; pass++) {       // V bf16
        int i = pass * 256 + t;
        int c = i & 63, j = i >> 6;
        g_Vb[(size_t)(w * 4096 + nbase + j) * 64 + c] = __float2bfloat16(xs[j * 66 + c]);
    }
    int lane = t & 31, warp = t >> 5;
    int j0 = warp * 2, j1 = j0 + 1;
    float mv0 = g_mvec[lane], mv1 = g_mvec[lane + 32];
    float u00 = 0.f, u01 = 0.f, u10 = 0.f, u11 = 0.f;
    const float2* w0p = (const float2*)(wT + lane * 66);
    const float2* w1p = (const float2*)(wT + (lane + 32) * 66);
    const float2* x0p = (const float2*)(xs + j0 * 66);
    const float2* x1p = (const float2*)(xs + j1 * 66);
#pragma unroll 8
    for (int cc = 0; cc < 32; cc++) {
        float2 wv0 = w0p[cc], wv1 = w1p[cc];
        float2 xv0 = x0p[cc], xv1 = x1p[cc];
        u00 = fmaf(wv0.x, xv0.x, u00); u00 = fmaf(wv0.y, xv0.y, u00);
        u01 = fmaf(wv1.x, xv0.x, u01); u01 = fmaf(wv1.y, xv0.y, u01);
        u10 = fmaf(wv0.x, xv1.x, u10); u10 = fmaf(wv0.y, xv1.y, u10);
        u11 = fmaf(wv1.x, xv1.x, u11); u11 = fmaf(wv1.y, xv1.y, u11);
    }
    u00 -= mv0; u01 -= mv1; u10 -= mv0; u11 -= mv1;
    float ss0 = u00 * u00 + u01 * u01;
    float ss1 = u10 * u10 + u11 * u11;
#pragma unroll
    for (int o = 16; o; o >>= 1) {
        ss0 += __shfl_xor_sync(0xFFFFFFFFu, ss0, o);
        ss1 += __shfl_xor_sync(0xFFFFFFFFu, ss1, o);
    }
    float r0 = rsqrtf(ss0 + 1e-24f), r1 = rsqrtf(ss1 + 1e-24f);
    __nv_bfloat16* q0p = g_Qb + (size_t)(w * 4096 + nbase + j0) * 64;
    __nv_bfloat16* q1p = g_Qb + (size_t)(w * 4096 + nbase + j1) * 64;
    q0p[lane] = __float2bfloat16(u00 * r0);
    q0p[lane + 32] = __float2bfloat16(u01 * r0);
    q1p[lane] = __float2bfloat16(u10 * r1);
    q1p[lane + 32] = __float2bfloat16(u11 * r1);
}

// ---------- mma helpers ----------
__device__ __forceinline__ void ldsm4(unsigned addr, unsigned& r0, unsigned& r1,
                                      unsigned& r2, unsigned& r3) {
    asm volatile("ldmatrix.sync.aligned.m8n8.x4.shared.b16 {%0,%1,%2,%3}, [%4];"
                 : "=r"(r0), "=r"(r1), "=r"(r2), "=r"(r3) : "r"(addr));
}
__device__ __forceinline__ void ldsm4t(unsigned addr, unsigned& r0, unsigned& r1,
                                       unsigned& r2, unsigned& r3) {
    asm volatile("ldmatrix.sync.aligned.m8n8.x4.trans.shared.b16 {%0,%1,%2,%3}, [%4];"
                 : "=r"(r0), "=r"(r1), "=r"(r2), "=r"(r3) : "r"(addr));
}
__device__ __forceinline__ void mma16816(float* c, const unsigned* a, unsigned b0, unsigned b1) {
    asm volatile("mma.sync.aligned.m16n8k16.row.col.f32.bf16.bf16.f32 "
                 "{%0,%1,%2,%3},{%4,%5,%6,%7},{%8,%9},{%0,%1,%2,%3};"
                 : "+f"(c[0]), "+f"(c[1]), "+f"(c[2]), "+f"(c[3])
                 : "r"(a[0]), "r"(a[1]), "r"(a[2]), "r"(a[3]), "r"(b0), "r"(b1));
}
__device__ __forceinline__ void mma_tf32(float* c, unsigned a0, unsigned a1, unsigned a2,
                                         unsigned a3, unsigned b0, unsigned b1) {
    asm volatile("mma.sync.aligned.m16n8k8.row.col.f32.tf32.tf32.f32 "
                 "{%0,%1,%2,%3},{%4,%5,%6,%7},{%8,%9},{%0,%1,%2,%3};"
                 : "+f"(c[0]), "+f"(c[1]), "+f"(c[2]), "+f"(c[3])
                 : "r"(a0), "r"(a1), "r"(a2), "r"(a3), "r"(b0), "r"(b1));
}

// ---------- attention: bf16 HMMA, 64q CTA x 4 warps, ILP2, double-buffered ----------
#define PITCHB 144       // bytes per smem row (72 bf16)
#define BUFB   36864     // one buffer: K(18432) + V(18432)
__global__ void __launch_bounds__(128, 2) attn_mma() {
    extern __shared__ char smx[];
    unsigned smU = (unsigned)__cvta_generic_to_shared(smx);
    int w = blockIdx.y;
    int qb = blockIdx.x * 64;
    int t = threadIdx.x, warp = t >> 5, lane = t & 31;
    int g = lane >> 2, tig = lane & 3;
    const __nv_bfloat16* Qg = g_Qb + (size_t)w * 4096 * 64;
    const __nv_bfloat16* Vg = g_Vb + (size_t)w * 4096 * 64;

    int q0 = qb + warp * 16;
    unsigned qa[4][4];
#pragma unroll
    for (int s = 0; s < 4; s++) {
        const __nv_bfloat16* bp = Qg + (q0 + g) * 64 + s * 16 + 2 * tig;
        qa[s][0] = *(const unsigned*)(bp);
        qa[s][1] = *(const unsigned*)(bp + 8 * 64);
        qa[s][2] = *(const unsigned*)(bp + 8);
        qa[s][3] = *(const unsigned*)(bp + 8 * 64 + 8);
    }

    float o[8][4];
#pragma unroll
    for (int i = 0; i < 8; i++)
#pragma unroll
        for (int jx = 0; jx < 4; jx++) o[i][jx] = 0.f;
    u64t rsA = 0ull, rsB = 0ull;

    int mi = lane >> 3, li = lane & 7;
    unsigned kOff = ((mi >> 1) * 8 + li) * PITCHB + (mi & 1) * 16;
    unsigned vOff = ((mi & 1) * 8 + li) * PITCHB + (mi >> 1) * 16;

    const u64t C18 = pk2(0.125f, 0.125f);
    const u64t K3 = pk2(0.1889038f, 0.1889038f);
    const u64t K2 = pk2(0.4964532f, 0.4964532f);
    const u64t K1 = pk2(1.0001804f, 1.0001804f);
    const u64t K0 = pk2(0.9999986f, 0.9999986f);

#define ISSUE(ch) do {                                                        \
        int _b = (ch) & 1;                                                    \
        unsigned _kd = smU + _b * BUFB, _vd = _kd + 18432;                    \
        const char* _ks = (const char*)(Qg + (ch) * 128 * 64);                \
        const char* _vs = (const char*)(Vg + (ch) * 128 * 64);                \
        _Pragma("unroll")                                                     \
        for (int _i = 0; _i < 8; _i++) {                                      \
            int _idx = t + _i * 128;                                          \
            int _r = _idx >> 3, _cg = _idx & 7;                               \
            unsigned _o = _r * PITCHB + _cg * 16;                             \
            unsigned _go = _r * 128 + _cg * 16;                               \
            cp16(_kd + _o, _ks + _go);                                        \
            cp16(_vd + _o, _vs + _go);                                        \
        }                                                                     \
        asm volatile("cp.async.commit_group;");                               \
    } while (0)

#define SOFTEXP(p0, p1, ea) do {                                              \
        u64t d0 = pk2(p0[0], p0[1]), d1 = pk2(p0[2], p0[3]);                  \
        u64t d2 = pk2(p1[0], p1[1]), d3 = pk2(p1[2], p1[3]);                  \
        u64t s0 = fma2(d0, C18, C18), s1 = fma2(d1, C18, C18);                \
        u64t s2 = fma2(d2, C18, C18), s3 = fma2(d3, C18, C18);                \
        u64t e0 = fma2(s0, K3, K2); e0 = fma2(s0, e0, K1); e0 = fma2(s0, e0, K0); \
        u64t e1 = fma2(s1, K3, K2); e1 = fma2(s1, e1, K1); e1 = fma2(s1, e1, K0); \
        u64t e2 = fma2(s2, K3, K2); e2 = fma2(s2, e2, K1); e2 = fma2(s2, e2, K0); \
        u64t e3 = fma2(s3, K3, K2); e3 = fma2(s3, e3, K1); e3 = fma2(s3, e3, K0); \
        rsA = add2(rsA, e0); rsB = add2(rsB, e1);                             \
        rsA = add2(rsA, e2); rsB = add2(rsB, e3);                             \
        float f0, f1;                                                         \
        upk2(e0, f0, f1); ea[0] = packbf(f0, f1);                             \
        upk2(e1, f0, f1); ea[1] = packbf(f0, f1);                             \
        upk2(e2, f0, f1); ea[2] = packbf(f0, f1);                             \
        upk2(e3, f0, f1); ea[3] = packbf(f0, f1);                             \
    } while (0)

    ISSUE(0);
    ISSUE(1);

    for (int ch = 0; ch < 32; ch++) {
        if (ch < 31) asm volatile("cp.async.wait_group 1;");
        else         asm volatile("cp.async.wait_group 0;");
        __syncthreads();
        unsigned ksU = smU + (ch & 1) * BUFB;
        unsigned vsU = ksU + 18432;

#pragma unroll
        for (int jp = 0; jp < 8; jp += 2) {
            float pA0[4] = {0.f, 0.f, 0.f, 0.f}, pA1[4] = {0.f, 0.f, 0.f, 0.f};
            float pB0[4] = {0.f, 0.f, 0.f, 0.f}, pB1[4] = {0.f, 0.f, 0.f, 0.f};
#pragma unroll
            for (int s = 0; s < 4; s++) {
                unsigned r0, r1, r2, r3;
                ldsm4(ksU + jp * (16 * PITCHB) + s * 32 + kOff, r0, r1, r2, r3);
                mma16816(pA0, qa[s], r0, r1);
                mma16816(pA1, qa[s], r2, r3);
                ldsm4(ksU + (jp + 1) * (16 * PITCHB) + s * 32 + kOff, r0, r1, r2, r3);
                mma16816(pB0, qa[s], r0, r1);
                mma16816(pB1, qa[s], r2, r3);
            }
            unsigned eaA[4], eaB[4];
            SOFTEXP(pA0, pA1, eaA);
            SOFTEXP(pB0, pB1, eaB);
#pragma unroll
            for (int cp = 0; cp < 4; cp++) {
                unsigned r0, r1, r2, r3;
                ldsm4t(vsU + jp * (16 * PITCHB) + cp * 32 + vOff, r0, r1, r2, r3);
                mma16816(o[2 * cp],     eaA, r0, r1);
                mma16816(o[2 * cp + 1], eaA, r2, r3);
                ldsm4t(vsU + (jp + 1) * (16 * PITCHB) + cp * 32 + vOff, r0, r1, r2, r3);
                mma16816(o[2 * cp],     eaB, r0, r1);
                mma16816(o[2 * cp + 1], eaB, r2, r3);
            }
        }
        __syncthreads();
        if (ch + 2 < 32) ISSUE(ch + 2);
    }

    float rs0a, rs0b, rs1a, rs1b;
    upk2(rsA, rs0a, rs0b); upk2(rsB, rs1a, rs1b);
    float rs0 = rs0a + rs0b, rs1 = rs1a + rs1b;
    rs0 += __shfl_xor_sync(0xFFFFFFFFu, rs0, 1);
    rs0 += __shfl_xor_sync(0xFFFFFFFFu, rs0, 2);
    rs1 += __shfl_xor_sync(0xFFFFFFFFu, rs1, 1);
    rs1 += __shfl_xor_sync(0xFFFFFFFFu, rs1, 2);
    float i0 = 1.f / rs0, i1 = 1.f / rs1;

    float* outp = g_attn + (size_t)(w * 4096 + q0) * 64;
#pragma unroll
    for (int c = 0; c < 8; c++) {
        int col = c * 8 + 2 * tig;
        *(float2*)(outp + g * 64 + col)       = make_float2(o[c][0] * i0, o[c][1] * i0);
        *(float2*)(outp + (g + 8) * 64 + col) = make_float2(o[c][2] * i1, o[c][3] * i1);
    }
}

// ---------- fused 1x1 conv (attn 64ch + unet 1ch) + bias + residual -> g_t ----------
// 512 blocks x 256 threads: block = 32 pixels, thread = (pixel, 8-co group)
__global__ void __launch_bounds__(256) convl_fused(const float* __restrict__ unet,
                                                   const float* __restrict__ x,
                                                   const float* __restrict__ bias) {
    __shared__ float w_s[4160];
    int t = threadIdx.x;
    for (int i = t; i < 4160; i += 256) w_s[i] = g_wlT[i];
    __syncthreads();
    int p = blockIdx.x * 32 + (t & 31);
    int co0 = (t >> 5) * 8;
    float acc[8];
#pragma unroll
    for (int i = 0; i < 8; i++) acc[i] = 0.f;
#pragma unroll 4
    for (int ci = 0; ci < 64; ci++) {
        float v = g_attn[ci * 16384 + p];
        const float4* wr = (const float4*)(w_s + ci * 64 + co0);
        float4 w0 = wr[0], w1 = wr[1];
        acc[0] = fmaf(w0.x, v, acc[0]); acc[1] = fmaf(w0.y, v, acc[1]);
        acc[2] = fmaf(w0.z, v, acc[2]); acc[3] = fmaf(w0.w, v, acc[3]);
        acc[4] = fmaf(w1.x, v, acc[4]); acc[5] = fmaf(w1.y, v, acc[5]);
        acc[6] = fmaf(w1.z, v, acc[6]); acc[7] = fmaf(w1.w, v, acc[7]);
    }
    {
        float v = unet[p];
        const float4* wr = (const float4*)(w_s + 64 * 64 + co0);
        float4 w0 = wr[0], w1 = wr[1];
        acc[0] = fmaf(w0.x, v, acc[0]); acc[1] = fmaf(w0.y, v, acc[1]);
        acc[2] = fmaf(w0.z, v, acc[2]); acc[3] = fmaf(w0.w, v, acc[3]);
        acc[4] = fmaf(w1.x, v, acc[4]); acc[5] = fmaf(w1.y, v, acc[5]);
        acc[6] = fmaf(w1.z, v, acc[6]); acc[7] = fmaf(w1.w, v, acc[7]);
    }
#pragma unroll
    for (int i = 0; i < 8; i++) {
        int co = co0 + i;
        g_t[co * 16384 + p] = x[co * 16384 + p] + acc[i] + bias[co];
    }
}

// ---------- 3x3 conv (dil D) via tf32 mma; FUSE: + 1x1 conv3 + bias + residual ----------
template <int D, bool FUSE>
__global__ void __launch_bounds__(256) conv_tf32(const float* __restrict__ in,
                                                 const float* __restrict__ wB,
                                                 const float* __restrict__ bias,
                                                 float* __restrict__ out,
                                                 const float* __restrict__ xres,
                                                 const float* __restrict__ b3) {
    constexpr int IH = 8 + 2 * D, IW = 16 + 2 * D, INW = 8 * IH * IW;
    extern __shared__ float sm[];
    float* As  = sm;           // [128 px][73]
    float* Bs  = sm + 9344;    // [64 co][73]
    float* in_s = sm + 14016;  // [8 ci][IH][IW]
    int t = threadIdx.x, warp = t >> 5, lane = t & 31;
    int g = lane >> 2, tig = lane & 3;
    int r0 = blockIdx.y * 8, c0 = blockIdx.x * 16;

    float o[8][4];
#pragma unroll
    for (int nb = 0; nb < 8; nb++) {
        float b0 = bias[nb * 8 + 2 * tig], b1 = bias[nb * 8 + 2 * tig + 1];
        o[nb][0] = b0; o[nb][1] = b1; o[nb][2] = b0; o[nb][3] = b1;
    }

    int px_b = t >> 1, y_b = px_b >> 4, x_b = px_b & 15;
    int ci0 = (t & 1) * 4;

    for (int grp = 0; grp < 8; grp++) {
        __syncthreads();
        for (int idx = t; idx < INW; idx += 256) {
            int ci = idx / (IH * IW), rem = idx - ci * (IH * IW);
            int rr = rem / IW, cc = rem - rr * IW;
            int gr = r0 - D + rr, gc = c0 - D + cc;
            float v = 0.f;
            if (gr >= 0 && gr < 128 && gc >= 0 && gc < 128)
                v = in[(grp * 8 + ci) * 16384 + gr * 128 + gc];
            in_s[idx] = v;
        }
#pragma unroll
        for (int pass = 0; pass < 18; pass++) {
            int idx = pass * 256 + t;
            int co = idx / 72, k = idx - co * 72;
            Bs[co * 73 + k] = wB[co * 576 + grp * 72 + k];
        }
        __syncthreads();
        {
            const float* ip = in_s + ci0 * (IH * IW) + y_b * IW + x_b;
            float* ap = As + px_b * 73 + ci0 * 9;
#pragma unroll
            for (int cq = 0; cq < 4; cq++)
#pragma unroll
                for (int kh = 0; kh < 3; kh++)
#pragma unroll
                    for (int kw = 0; kw < 3; kw++)
                        ap[cq * 9 + kh * 3 + kw] = __uint_as_float(
                            cvt_tf32(ip[cq * IH * IW + (kh * D) * IW + kw * D]));
        }
        __syncthreads();
        const float* Ar = As + warp * 16 * 73;
#pragma unroll
        for (int kc = 0; kc < 9; kc++) {
            unsigned a0 = __float_as_uint(Ar[g * 73 + kc * 8 + tig]);
            unsigned a1 = __float_as_uint(Ar[(g + 8) * 73 + kc * 8 + tig]);
            unsigned a2 = __float_as_uint(Ar[g * 73 + kc * 8 + tig + 4]);
            unsigned a3 = __float_as_uint(Ar[(g + 8) * 73 + kc * 8 + tig + 4]);
#pragma unroll
            for (int nb = 0; nb < 8; nb++) {
                unsigned b0 = __float_as_uint(Bs[(nb * 8 + g) * 73 + kc * 8 + tig]);
                unsigned b1 = __float_as_uint(Bs[(nb * 8 + g) * 73 + kc * 8 + tig + 4]);
                mma_tf32(o[nb], a0, a1, a2, a3, b0, b1);
            }
        }
    }

    if (!FUSE) {
        int gp = (r0 + warp) * 128 + c0;
#pragma unroll
        for (int nb = 0; nb < 8; nb++) {
            int co = nb * 8 + 2 * tig;
            out[co * 16384 + gp + g]           = fmaxf(o[nb][0], 0.f);
            out[(co + 1) * 16384 + gp + g]     = fmaxf(o[nb][1], 0.f);
            out[co * 16384 + gp + g + 8]       = fmaxf(o[nb][2], 0.f);
            out[(co + 1) * 16384 + gp + g + 8] = fmaxf(o[nb][3], 0.f);
        }
    } else {
        __syncthreads();
#pragma unroll
        for (int nb = 0; nb < 8; nb++) {
            int co = nb * 8 + 2 * tig;
            As[(warp * 16 + g) * 65 + co]         = fmaxf(o[nb][0], 0.f);
            As[(warp * 16 + g) * 65 + co + 1]     = fmaxf(o[nb][1], 0.f);
            As[(warp * 16 + g + 8) * 65 + co]     = fmaxf(o[nb][2], 0.f);
            As[(warp * 16 + g + 8) * 65 + co + 1] = fmaxf(o[nb][3], 0.f);
        }
#pragma unroll
        for (int pass = 0; pass < 16; pass++) {
            int idx = pass * 256 + t;
            Bs[(idx >> 6) * 65 + (idx & 63)] = g_w3c[idx];
        }
        __syncthreads();
        float o2[8][4];
#pragma unroll
        for (int nb = 0; nb < 8; nb++) {
            float b0 = b3[nb * 8 + 2 * tig], b1 = b3[nb * 8 + 2 * tig + 1];
            o2[nb][0] = b0; o2[nb][1] = b1; o2[nb][2] = b0; o2[nb][3] = b1;
        }
        const float* Ar2 = As + warp * 16 * 65;
#pragma unroll
        for (int kc = 0; kc < 8; kc++) {
            unsigned a0 = cvt_tf32(Ar2[g * 65 + kc * 8 + tig]);
            unsigned a1 = cvt_tf32(Ar2[(g + 8) * 65 + kc * 8 + tig]);
            unsigned a2 = cvt_tf32(Ar2[g * 65 + kc * 8 + tig + 4]);
            unsigned a3 = cvt_tf32(Ar2[(g + 8) * 65 + kc * 8 + tig + 4]);
#pragma unroll
            for (int nb = 0; nb < 8; nb++) {
                unsigned b0 = __float_as_uint(Bs[(nb * 8 + g) * 65 + kc * 8 + tig]);
                unsigned b1 = __float_as_uint(Bs[(nb * 8 + g) * 65 + kc * 8 + tig + 4]);
                mma_tf32(o2[nb], a0, a1, a2, a3, b0, b1);
            }
        }
        int gp = (r0 + warp) * 128 + c0;
#pragma unroll
        for (int nb = 0; nb < 8; nb++) {
            int co = nb * 8 + 2 * tig;
            out[co * 16384 + gp + g]           = xres[co * 16384 + gp + g]           + o2[nb][0];
            out[(co + 1) * 16384 + gp + g]     = xres[(co + 1) * 16384 + gp + g]     + o2[nb][1];
            out[co * 16384 + gp + g + 8]       = xres[co * 16384 + gp + g + 8]       + o2[nb][2];
            out[(co + 1) * 16384 + gp + g + 8] = xres[(co + 1) * 16384 + gp + g + 8] + o2[nb][3];
        }
    }
}

extern "C" void kernel_launch(void* const* d_in, const int* in_sizes, int n_in,
                              void* d_out, int out_size) {
    const float* x     = (const float*)d_in[0];
    const float* unet  = (const float*)d_in[1];
    const float* wqk   = (const float*)d_in[2];
    const float* c1w   = (const float*)d_in[3];
    const float* c1b   = (const float*)d_in[4];
    const float* c2w   = (const float*)d_in[5];
    const float* c2b   = (const float*)d_in[6];
    const float* c3w   = (const float*)d_in[7];
    const float* c3b   = (const float*)d_in[8];
    const float* clw   = (const float*)d_in[9];
    const float* clb   = (const float*)d_in[10];
    float* out = (float*)d_out;

    int smem1 = (14016 + 8 * 10 * 18) * 4;
    int smem2 = (14016 + 8 * 12 * 20) * 4;
    cudaFuncSetAttribute(attn_mma, cudaFuncAttributeMaxDynamicSharedMemorySize, 2 * BUFB);
    cudaFuncSetAttribute(conv_tf32<1, false>, cudaFuncAttributeMaxDynamicSharedMemorySize, smem1);
    cudaFuncSetAttribute(conv_tf32<2, true>,  cudaFuncAttributeMaxDynamicSharedMemorySize, smem2);

    prep_all<<<144, 256>>>(x, c1w, c2w, c3w, clw, wqk);
    qv_build<<<1024, 256>>>(x, wqk);
    attn_mma<<<dim3(64, 4), 128, 2 * BUFB>>>();
    convl_fused<<<512, 256>>>(unet, x, clb);
    float* z1;  cudaGetSymbolAddress((void**)&z1, g_z1);
    float* tt;  cudaGetSymbolAddress((void**)&tt, g_t);
    float* wc1; cudaGetSymbolAddress((void**)&wc1, g_wc1);
    float* wc2; cudaGetSymbolAddress((void**)&wc2, g_wc2);
    conv_tf32<1, false><<<dim3(8, 16), 256, smem1>>>(tt, wc1, c1b, z1, nullptr, nullptr);
    conv_tf32<2, true><<<dim3(8, 16), 256, smem2>>>(z1, wc2, c2b, out, x, c3b);
}